// round 10
// baseline (speedup 1.0000x reference)
#include <cuda_runtime.h>
#include <stdint.h>
#include <math.h>

// B=32, N=64, ATTR=4, STATE=8, REL=4, GDIM=32, NF=128, pstep=2
#define NNODES 2048

// ---------------- scratch (static device memory) ----------------
__device__ float g_E[2048 * 64 * 128];     // E = W_rel @ rel_encode, [bi][j][f] (64 MB)
__device__ float g_obj[2048 * 128];
__device__ float g_u[2048 * 128];
__device__ float g_vt[32 * 128 * 64];      // [b][k][n]
__device__ float g_R[2048 * 128];
__device__ float g_S[2048 * 128];
__device__ float g_agg[2048 * 128];
__device__ float g_w1k[128 * 128];         // re_w1 [f][k], tf32-rounded
__device__ float g_wrk[128 * 128];         // rp_w rel-block [f][k], tf32-rounded

__device__ __forceinline__ float to_tf32(float x) {
    float r;
    asm("cvt.rna.tf32.f32 %0, %1;" : "=f"(r) : "f"(x));
    return r;
}

#define LDSM_X4(r, addr)                                                      \
    asm volatile("ldmatrix.sync.aligned.m8n8.x4.shared.b16 {%0,%1,%2,%3}, [%4];" \
                 : "=r"((r)[0]), "=r"((r)[1]), "=r"((r)[2]), "=r"((r)[3])     \
                 : "r"(addr))

#define MMA_TF32(d, a, b0v, b1v)                                              \
    asm volatile(                                                             \
        "mma.sync.aligned.m16n8k8.row.col.f32.tf32.tf32.f32 "                 \
        "{%0,%1,%2,%3}, {%4,%5,%6,%7}, {%8,%9}, {%0,%1,%2,%3};"               \
        : "+f"((d)[0]), "+f"((d)[1]), "+f"((d)[2]), "+f"((d)[3])              \
        : "r"((a)[0]), "r"((a)[1]), "r"((a)[2]), "r"((a)[3]),                 \
          "r"(b0v), "r"(b1v))

// ---------------- weight prep: tf32 rounding of the two MMA weights ----------------
__global__ void prep_kernel(const float* __restrict__ re_w1,
                            const float* __restrict__ rp_w) {
    int m = blockIdx.x;
    int t = threadIdx.x;
    if (m == 0) {
        for (int i = t; i < 128 * 128; i += 256) g_w1k[i] = to_tf32(re_w1[i]);
    } else {
        for (int i = t; i < 128 * 128; i += 256) {
            int f = i >> 7, k = i & 127;
            g_wrk[i] = to_tf32(rp_w[f * 384 + k]);
        }
    }
}

// ---------------- fused node_pre + obj_encode + rs(step0): 8 nodes/block ----------------
__global__ __launch_bounds__(128) void encode_all(const float* __restrict__ attrs,
                                                  const float* __restrict__ states,
                                                  const float* __restrict__ re_w0,
                                                  const float* __restrict__ re_b0,
                                                  const float* __restrict__ oe_w0,
                                                  const float* __restrict__ oe_b0,
                                                  const float* __restrict__ oe_w1,
                                                  const float* __restrict__ oe_b1,
                                                  const float* __restrict__ rp_w,
                                                  const float* __restrict__ rp_b) {
    __shared__ float sa[8][4];
    __shared__ float ssm[8][8];
    __shared__ float Hs1[8][128];
    __shared__ float Os[8][128];
    int base = blockIdx.x * 8;
    int f = threadIdx.x;
    if (f < 32) {
        int n = f >> 2, c = f & 3;
        sa[n][c] = attrs[(base + n) * 4 + c];
    } else if (f < 96) {
        int q = f - 32;
        int n = q >> 3, c = q & 7;
        ssm[n][c] = states[(base + n) * 8 + c];
    }
    __syncthreads();
    // ---- node_pre ----
    {
        const float* w = re_w0 + f * 20;
        float ws[8], wr4[4], ws4[4];
#pragma unroll
        for (int c = 0; c < 8; c++) ws[c] = w[4 + c];
#pragma unroll
        for (int c = 0; c < 4; c++) { wr4[c] = w[12 + c]; ws4[c] = w[16 + c]; }
        float b0 = re_b0[f];
        int b = base >> 6;
#pragma unroll
        for (int n = 0; n < 8; n++) {
            float u = b0, v = 0.f;
#pragma unroll
            for (int c = 0; c < 8; c++) {
                u += ws[c] * ssm[n][c];
                v -= ws[c] * ssm[n][c];
            }
#pragma unroll
            for (int c = 0; c < 4; c++) {
                u += wr4[c] * sa[n][c];
                v += ws4[c] * sa[n][c];
            }
            int node = base + n;
            g_u[node * 128 + f] = u;
            g_vt[(b * 128 + f) * 64 + (node & 63)] = v;
        }
    }
    // ---- obj encoder layer0 ----
    {
        float w0r[12];
#pragma unroll
        for (int c = 0; c < 12; c++) w0r[c] = oe_w0[f * 12 + c];
        float b0 = oe_b0[f];
#pragma unroll
        for (int n = 0; n < 8; n++) {
            float h = b0;
#pragma unroll
            for (int c = 0; c < 4; c++) h += w0r[c] * sa[n][c];
#pragma unroll
            for (int c = 0; c < 8; c++) h += w0r[4 + c] * ssm[n][c];
            Hs1[n][f] = fmaxf(h, 0.f);
        }
    }
    __syncthreads();
    // ---- obj encoder layer1 ----
    {
        float acc[8] = {0, 0, 0, 0, 0, 0, 0, 0};
#pragma unroll 4
        for (int k = 0; k < 128; k += 4) {
            float4 w = *(const float4*)&oe_w1[f * 128 + k];
#pragma unroll
            for (int n = 0; n < 8; n++) {
                float4 x = *(const float4*)&Hs1[n][k];
                acc[n] += w.x * x.x + w.y * x.y + w.z * x.z + w.w * x.w;
            }
        }
        float b1 = oe_b1[f];
#pragma unroll
        for (int n = 0; n < 8; n++) {
            float o = fmaxf(acc[n] + b1, 0.f);
            Os[n][f] = o;
            g_obj[(base + n) * 128 + f] = o;
        }
    }
    __syncthreads();
    // ---- rs step 0 ----
    {
        float r[8] = {0, 0, 0, 0, 0, 0, 0, 0};
        float s[8] = {0, 0, 0, 0, 0, 0, 0, 0};
        const float* wrow = rp_w + f * 384;
#pragma unroll 4
        for (int k = 0; k < 128; k += 4) {
            float4 wr = *(const float4*)&wrow[128 + k];
            float4 ws = *(const float4*)&wrow[256 + k];
#pragma unroll
            for (int n = 0; n < 8; n++) {
                float4 o = *(const float4*)&Os[n][k];
                r[n] += wr.x * o.x + wr.y * o.y + wr.z * o.z + wr.w * o.w;
                s[n] += ws.x * o.x + ws.y * o.y + ws.z * o.z + ws.w * o.w;
            }
        }
        float bb = rp_b[f];
#pragma unroll
        for (int n = 0; n < 8; n++) {
            g_R[(base + n) * 128 + f] = r[n] + bb;
            g_S[(base + n) * 128 + f] = s[n];
        }
    }
}

// ---------------- fused rel encoder + edge-GEMM + edge-apply(step0) ----------------
__global__ __launch_bounds__(512) void rel_fused_tc(const float* __restrict__ rel_attrs,
                                                    const float* __restrict__ re_w0,
                                                    const float* __restrict__ re_b1,
                                                    const float* __restrict__ rp_lnw,
                                                    const float* __restrict__ rp_lnb) {
    extern __shared__ float dsm[];
    float* Hs = dsm;                    // 256 x 132
    float* Wsm = dsm + 33792;           // 128 x 132
    float* Us = dsm + 50688;            // 4 x 128 (reused as Rs in edge-apply)
    float* Bs = dsm + 51200;            // 128
    int bi0 = blockIdx.x * 4;
    int tid = threadIdx.x;
    int b = bi0 >> 6;
    int lane = tid & 31, warp = tid >> 5;
    int jg = warp >> 1;
    int ng = warp & 1;
    uint32_t hs_base = (uint32_t)__cvta_generic_to_shared(Hs);
    uint32_t w_base = (uint32_t)__cvta_generic_to_shared(Wsm);

    Us[tid] = g_u[(bi0 + (tid >> 7)) * 128 + (tid & 127)];
    if (tid < 128) Bs[tid] = re_b1[tid];
#pragma unroll 4
    for (int i = 0; i < 8; i++) {
        int idx = (i * 512 + tid) * 4;
        float4 v = *(const float4*)&g_w1k[idx];
        *(float4*)&Wsm[(idx >> 7) * 132 + (idx & 127)] = v;
    }
    __syncthreads();

    // ---- build H[r][k] (tf32) ----
    {
        int bi_l = tid >> 7;
        int j = (tid >> 1) & 63;
        int kh = tid & 1;
        float4 rv = *(const float4*)(rel_attrs + ((bi0 + bi_l) * 64 + j) * 4);
        const float* vt = g_vt + b * 8192 + j;
        const float* uu = Us + bi_l * 128;
        float* hrow = Hs + (bi_l * 64 + j) * 132;
#pragma unroll 4
        for (int kk = 0; kk < 64; kk++) {
            int k = kh * 64 + kk;
            const float* w = re_w0 + k * 20;
            float val = uu[k] + vt[k * 64] + rv.x * w[0] + rv.y * w[1] + rv.z * w[2] + rv.w * w[3];
            hrow[k] = to_tf32(fmaxf(val, 0.f));
        }
    }
    __syncthreads();

    uint32_t aAddr = hs_base + 4 * ((32 * jg + (lane & 15)) * 132 + 4 * (lane >> 4));
    uint32_t bAddr = w_base + 4 * ((64 * ng + (lane & 7)) * 132 + 4 * (lane >> 3));
    float d[2][8][4];

    // ================= GEMM1 =================
#pragma unroll
    for (int m = 0; m < 2; m++)
#pragma unroll
        for (int n = 0; n < 8; n++)
#pragma unroll
            for (int q = 0; q < 4; q++) d[m][n][q] = 0.f;
#pragma unroll
    for (int c = 0; c < 8; c++) {
        int k0 = c * 16;
        uint32_t a[2][2][4];
#pragma unroll
        for (int m = 0; m < 2; m++)
#pragma unroll
            for (int s = 0; s < 2; s++)
                LDSM_X4(a[m][s], aAddr + 4 * (m * 16 * 132 + k0 + 8 * s));
#pragma unroll
        for (int h = 0; h < 2; h++) {
            uint32_t bb[4][4];
#pragma unroll
            for (int n4 = 0; n4 < 4; n4++)
                LDSM_X4(bb[n4], bAddr + 4 * ((h * 4 + n4) * 8 * 132 + k0));
#pragma unroll
            for (int s = 0; s < 2; s++)
#pragma unroll
                for (int n4 = 0; n4 < 4; n4++) {
                    MMA_TF32(d[0][h * 4 + n4], a[0][s], bb[n4][2 * s], bb[n4][2 * s + 1]);
                    MMA_TF32(d[1][h * 4 + n4], a[1][s], bb[n4][2 * s], bb[n4][2 * s + 1]);
                }
        }
    }
    __syncthreads();

    // epilogue 1
#pragma unroll
    for (int m = 0; m < 2; m++) {
        int r0 = 32 * jg + 16 * m + (lane >> 2);
#pragma unroll
        for (int n = 0; n < 8; n++) {
            int f0 = 64 * ng + 8 * n + 2 * (lane & 3);
            float bb0 = Bs[f0], bb1 = Bs[f0 + 1];
            Hs[r0 * 132 + f0]           = to_tf32(fmaxf(d[m][n][0] + bb0, 0.f));
            Hs[r0 * 132 + f0 + 1]       = to_tf32(fmaxf(d[m][n][1] + bb1, 0.f));
            Hs[(r0 + 8) * 132 + f0]     = to_tf32(fmaxf(d[m][n][2] + bb0, 0.f));
            Hs[(r0 + 8) * 132 + f0 + 1] = to_tf32(fmaxf(d[m][n][3] + bb1, 0.f));
        }
    }
#pragma unroll 4
    for (int i = 0; i < 8; i++) {
        int idx = (i * 512 + tid) * 4;
        float4 v = *(const float4*)&g_wrk[idx];
        *(float4*)&Wsm[(idx >> 7) * 132 + (idx & 127)] = v;
    }
    __syncthreads();

    // ================= GEMM2 =================
#pragma unroll
    for (int m = 0; m < 2; m++)
#pragma unroll
        for (int n = 0; n < 8; n++)
#pragma unroll
            for (int q = 0; q < 4; q++) d[m][n][q] = 0.f;
#pragma unroll
    for (int c = 0; c < 8; c++) {
        int k0 = c * 16;
        uint32_t a[2][2][4];
#pragma unroll
        for (int m = 0; m < 2; m++)
#pragma unroll
            for (int s = 0; s < 2; s++)
                LDSM_X4(a[m][s], aAddr + 4 * (m * 16 * 132 + k0 + 8 * s));
#pragma unroll
        for (int h = 0; h < 2; h++) {
            uint32_t bb[4][4];
#pragma unroll
            for (int n4 = 0; n4 < 4; n4++)
                LDSM_X4(bb[n4], bAddr + 4 * ((h * 4 + n4) * 8 * 132 + k0));
#pragma unroll
            for (int s = 0; s < 2; s++)
#pragma unroll
                for (int n4 = 0; n4 < 4; n4++) {
                    MMA_TF32(d[0][h * 4 + n4], a[0][s], bb[n4][2 * s], bb[n4][2 * s + 1]);
                    MMA_TF32(d[1][h * 4 + n4], a[1][s], bb[n4][2 * s], bb[n4][2 * s + 1]);
                }
        }
    }
    __syncthreads();

    // epilogue 2: store E to gmem AND into Hs
    float* Ep = g_E + (long)bi0 * 8192;
#pragma unroll
    for (int m = 0; m < 2; m++) {
        int r0 = 32 * jg + 16 * m + (lane >> 2);
#pragma unroll
        for (int n = 0; n < 8; n++) {
            int f0 = 64 * ng + 8 * n + 2 * (lane & 3);
            *(float2*)&Ep[r0 * 128 + f0] = make_float2(d[m][n][0], d[m][n][1]);
            *(float2*)&Ep[(r0 + 8) * 128 + f0] = make_float2(d[m][n][2], d[m][n][3]);
            *(float2*)&Hs[r0 * 132 + f0] = make_float2(d[m][n][0], d[m][n][1]);
            *(float2*)&Hs[(r0 + 8) * 132 + f0] = make_float2(d[m][n][2], d[m][n][3]);
        }
    }
    float* Ss = Wsm;            // 8192 floats
    float* Ps = Wsm + 8192;     // 2048 floats
#pragma unroll
    for (int i = 0; i < 4; i++) {
        int idx4 = (i * 512 + tid) * 4;
        *(float4*)&Ss[idx4] = *(const float4*)&g_S[b * 8192 + idx4];
    }
    Us[tid] = g_R[bi0 * 128 + tid];
    __syncthreads();

    // ---- fused edge-apply step 0 ----
    {
        int bi_l = warp >> 2;
        float4 rv = *(const float4*)&Us[bi_l * 128 + lane * 4];
        float4 lw = *(const float4*)&rp_lnw[lane * 4];
        float4 lb = *(const float4*)&rp_lnb[lane * 4];
        float ag0 = 0.f, ag1 = 0.f, ag2 = 0.f, ag3 = 0.f;
#pragma unroll 4
        for (int rr = 0; rr < 16; rr++) {
            int r = warp * 16 + rr;
            int j = r & 63;
            float4 e = *(const float4*)&Hs[r * 132 + lane * 4];
            float4 sv = *(const float4*)&Ss[j * 128 + lane * 4];
            float4 y = make_float4(e.x + rv.x + sv.x, e.y + rv.y + sv.y,
                                   e.z + rv.z + sv.z, e.w + rv.w + sv.w);
            float s = y.x + y.y + y.z + y.w;
            float ss = y.x * y.x + y.y * y.y + y.z * y.z + y.w * y.w;
#pragma unroll
            for (int off = 16; off; off >>= 1) {
                s += __shfl_xor_sync(0xffffffffu, s, off);
                ss += __shfl_xor_sync(0xffffffffu, ss, off);
            }
            float mu = s * 0.0078125f;
            float var = ss * 0.0078125f - mu * mu;
            float rstd = rsqrtf(var + 1e-5f);
            ag0 += fmaxf((y.x - mu) * rstd * lw.x + lb.x, 0.f);
            ag1 += fmaxf((y.y - mu) * rstd * lw.y + lb.y, 0.f);
            ag2 += fmaxf((y.z - mu) * rstd * lw.z + lb.z, 0.f);
            ag3 += fmaxf((y.w - mu) * rstd * lw.w + lb.w, 0.f);
        }
        *(float4*)&Ps[warp * 128 + lane * 4] = make_float4(ag0, ag1, ag2, ag3);
    }
    __syncthreads();
    {
        int bi_l = tid >> 7, f = tid & 127;
        g_agg[(bi0 + bi_l) * 128 + f] =
            Ps[(4 * bi_l) * 128 + f] + Ps[(4 * bi_l + 1) * 128 + f] +
            Ps[(4 * bi_l + 2) * 128 + f] + Ps[(4 * bi_l + 3) * 128 + f];
    }
}

// ---------------- object update + rs (step0->1): 4 nodes/block, grid 512 ----------------
__global__ __launch_bounds__(128) void obj_update_rs(const float* __restrict__ pp_w,
                                                     const float* __restrict__ pp_b,
                                                     const float* __restrict__ pp_lnw,
                                                     const float* __restrict__ pp_lnb,
                                                     const float* __restrict__ rp_w,
                                                     const float* __restrict__ rp_b) {
    __shared__ float Xs[4][256];
    __shared__ float Cs[4][132];
    __shared__ float Os2[4][128];
    int base = blockIdx.x * 4;
    int f = threadIdx.x;
#pragma unroll
    for (int n = 0; n < 4; n++) {
        Xs[n][f] = g_obj[(base + n) * 128 + f];
        Xs[n][128 + f] = g_agg[(base + n) * 128 + f];
    }
    __syncthreads();
    float acc[4] = {0, 0, 0, 0};
    const float* wrow = pp_w + f * 256;
#pragma unroll 4
    for (int k = 0; k < 256; k += 4) {
        float4 w = *(const float4*)&wrow[k];
#pragma unroll
        for (int n = 0; n < 4; n++) {
            float4 x = *(const float4*)&Xs[n][k];
            acc[n] += w.x * x.x + w.y * x.y + w.z * x.z + w.w * x.w;
        }
    }
    float bb = pp_b[f];
#pragma unroll
    for (int n = 0; n < 4; n++) Cs[n][f] = acc[n] + bb;
    __syncthreads();
    {
        int warp = f >> 5, lane = f & 31;
        float4 lw = *(const float4*)&pp_lnw[lane * 4];
        float4 lb = *(const float4*)&pp_lnb[lane * 4];
        int n = warp;
        float4 y = *(const float4*)&Cs[n][lane * 4];
        float s = y.x + y.y + y.z + y.w;
        float ss = y.x * y.x + y.y * y.y + y.z * y.z + y.w * y.w;
#pragma unroll
        for (int off = 16; off; off >>= 1) {
            s += __shfl_xor_sync(0xffffffffu, s, off);
            ss += __shfl_xor_sync(0xffffffffu, ss, off);
        }
        float mu = s * 0.0078125f;
        float var = ss * 0.0078125f - mu * mu;
        float rstd = rsqrtf(var + 1e-5f);
        float4 o = make_float4(fmaxf((y.x - mu) * rstd * lw.x + lb.x, 0.f),
                               fmaxf((y.y - mu) * rstd * lw.y + lb.y, 0.f),
                               fmaxf((y.z - mu) * rstd * lw.z + lb.z, 0.f),
                               fmaxf((y.w - mu) * rstd * lw.w + lb.w, 0.f));
        *(float4*)&Os2[n][lane * 4] = o;
        *(float4*)&g_obj[(base + n) * 128 + lane * 4] = o;
    }
    __syncthreads();
    // ---- rs for step 1 ----
    float r[4] = {0, 0, 0, 0};
    float s2[4] = {0, 0, 0, 0};
    const float* wr_row = rp_w + f * 384;
#pragma unroll 4
    for (int k = 0; k < 128; k += 4) {
        float4 wr = *(const float4*)&wr_row[128 + k];
        float4 ws = *(const float4*)&wr_row[256 + k];
#pragma unroll
        for (int n = 0; n < 4; n++) {
            float4 o = *(const float4*)&Os2[n][k];
            r[n] += wr.x * o.x + wr.y * o.y + wr.z * o.z + wr.w * o.w;
            s2[n] += ws.x * o.x + ws.y * o.y + ws.z * o.z + ws.w * o.w;
        }
    }
    float rb = rp_b[f];
#pragma unroll
    for (int n = 0; n < 4; n++) {
        g_R[(base + n) * 128 + f] = r[n] + rb;
        g_S[(base + n) * 128 + f] = s2[n];
    }
}

// ---------------- final fused: edge-apply(step1) + obj_update + predict, 4 bi/block ----------------
__global__ __launch_bounds__(128) void final_fused(const float* __restrict__ rp_lnw,
                                                   const float* __restrict__ rp_lnb,
                                                   const float* __restrict__ pp_w,
                                                   const float* __restrict__ pp_b,
                                                   const float* __restrict__ pp_lnw,
                                                   const float* __restrict__ pp_lnb,
                                                   const float* __restrict__ pr_w0,
                                                   const float* __restrict__ pr_b0,
                                                   const float* __restrict__ pr_w1,
                                                   const float* __restrict__ pr_b1,
                                                   float* __restrict__ out) {
    __shared__ float Xs[4][256];
    __shared__ float Cs[4][132];
    __shared__ float Os2[4][128];
    __shared__ float Hs2[4][128];
    int bi0 = blockIdx.x * 4;
    int b = bi0 >> 6;
    int tid = threadIdx.x;
    int warp = tid >> 5, lane = tid & 31;

    // ---- edge-apply step 1: warp w handles bi0+w (64 rows) ----
    {
        int bi = bi0 + warp;
        float4 rv = *(const float4*)&g_R[bi * 128 + lane * 4];
        float4 lw = *(const float4*)&rp_lnw[lane * 4];
        float4 lb = *(const float4*)&rp_lnb[lane * 4];
        const float* Ep = g_E + (long)bi * 8192;
        float ag0 = 0.f, ag1 = 0.f, ag2 = 0.f, ag3 = 0.f;
#pragma unroll 4
        for (int j = 0; j < 64; j++) {
            float4 e = *(const float4*)&Ep[j * 128 + lane * 4];
            float4 sv = *(const float4*)&g_S[(b * 64 + j) * 128 + lane * 4];
            float4 y = make_float4(e.x + rv.x + sv.x, e.y + rv.y + sv.y,
                                   e.z + rv.z + sv.z, e.w + rv.w + sv.w);
            float s = y.x + y.y + y.z + y.w;
            float ss = y.x * y.x + y.y * y.y + y.z * y.z + y.w * y.w;
#pragma unroll
            for (int off = 16; off; off >>= 1) {
                s += __shfl_xor_sync(0xffffffffu, s, off);
                ss += __shfl_xor_sync(0xffffffffu, ss, off);
            }
            float mu = s * 0.0078125f;
            float var = ss * 0.0078125f - mu * mu;
            float rstd = rsqrtf(var + 1e-5f);
            ag0 += fmaxf((y.x - mu) * rstd * lw.x + lb.x, 0.f);
            ag1 += fmaxf((y.y - mu) * rstd * lw.y + lb.y, 0.f);
            ag2 += fmaxf((y.z - mu) * rstd * lw.z + lb.z, 0.f);
            ag3 += fmaxf((y.w - mu) * rstd * lw.w + lb.w, 0.f);
        }
        // agg for node bi goes to Xs[warp][128..255]
        *(float4*)&Xs[warp][128 + lane * 4] = make_float4(ag0, ag1, ag2, ag3);
    }
    {
        int f = tid;
#pragma unroll
        for (int n = 0; n < 4; n++) Xs[n][f] = g_obj[(bi0 + n) * 128 + f];
    }
    __syncthreads();

    // ---- obj update (no g_obj writeback needed) ----
    {
        int f = tid;
        float acc[4] = {0, 0, 0, 0};
        const float* wrow = pp_w + f * 256;
#pragma unroll 4
        for (int k = 0; k < 256; k += 4) {
            float4 w = *(const float4*)&wrow[k];
#pragma unroll
            for (int n = 0; n < 4; n++) {
                float4 x = *(const float4*)&Xs[n][k];
                acc[n] += w.x * x.x + w.y * x.y + w.z * x.z + w.w * x.w;
            }
        }
        float bb = pp_b[f];
#pragma unroll
        for (int n = 0; n < 4; n++) Cs[n][f] = acc[n] + bb;
    }
    __syncthreads();
    {
        float4 lw = *(const float4*)&pp_lnw[lane * 4];
        float4 lb = *(const float4*)&pp_lnb[lane * 4];
        int n = warp;
        float4 y = *(const float4*)&Cs[n][lane * 4];
        float s = y.x + y.y + y.z + y.w;
        float ss = y.x * y.x + y.y * y.y + y.z * y.z + y.w * y.w;
#pragma unroll
        for (int off = 16; off; off >>= 1) {
            s += __shfl_xor_sync(0xffffffffu, s, off);
            ss += __shfl_xor_sync(0xffffffffu, ss, off);
        }
        float mu = s * 0.0078125f;
        float var = ss * 0.0078125f - mu * mu;
        float rstd = rsqrtf(var + 1e-5f);
        float4 o = make_float4(fmaxf((y.x - mu) * rstd * lw.x + lb.x, 0.f),
                               fmaxf((y.y - mu) * rstd * lw.y + lb.y, 0.f),
                               fmaxf((y.z - mu) * rstd * lw.z + lb.z, 0.f),
                               fmaxf((y.w - mu) * rstd * lw.w + lb.w, 0.f));
        *(float4*)&Os2[n][lane * 4] = o;
    }
    __syncthreads();

    // ---- predict layer1 ----
    {
        int f = tid;
        float acc[4] = {0, 0, 0, 0};
        const float* w0row = pr_w0 + f * 128;
#pragma unroll 4
        for (int k = 0; k < 128; k += 4) {
            float4 w = *(const float4*)&w0row[k];
#pragma unroll
            for (int n = 0; n < 4; n++) {
                float4 x = *(const float4*)&Os2[n][k];
                acc[n] += w.x * x.x + w.y * x.y + w.z * x.z + w.w * x.w;
            }
        }
        float b0 = pr_b0[f];
#pragma unroll
        for (int n = 0; n < 4; n++) Hs2[n][f] = fmaxf(acc[n] + b0, 0.f);
    }
    __syncthreads();
    // ---- predict layer2: 4 nodes x 32 outs = 128 outputs, one per thread ----
    {
        int n = tid >> 5, op = tid & 31;
        float a0 = 0.f;
        const float* wp = pr_w1 + op * 128;
#pragma unroll 4
        for (int k = 0; k < 128; k += 4) {
            float4 x = *(const float4*)&Hs2[n][k];
            float4 w = *(const float4*)&wp[k];
            a0 += w.x * x.x + w.y * x.y + w.z * x.z + w.w * x.w;
        }
        out[(bi0 + n) * 32 + op] = tanhf(a0 + pr_b1[op]);
    }
}

// ---------------- launch ----------------
extern "C" void kernel_launch(void* const* d_in, const int* in_sizes, int n_in,
                              void* d_out, int out_size) {
    const float* attrs     = (const float*)d_in[0];
    const float* states    = (const float*)d_in[1];
    const float* rel_attrs = (const float*)d_in[3];
    const float* oe_w0 = (const float*)d_in[4];
    const float* oe_b0 = (const float*)d_in[5];
    const float* oe_w1 = (const float*)d_in[6];
    const float* oe_b1 = (const float*)d_in[7];
    const float* re_w0 = (const float*)d_in[8];
    const float* re_b0 = (const float*)d_in[9];
    const float* re_w1 = (const float*)d_in[10];
    const float* re_b1 = (const float*)d_in[11];
    const float* rp_w  = (const float*)d_in[12];
    const float* rp_b  = (const float*)d_in[13];
    const float* rp_lnw = (const float*)d_in[14];
    const float* rp_lnb = (const float*)d_in[15];
    const float* pp_w  = (const float*)d_in[16];
    const float* pp_b  = (const float*)d_in[17];
    const float* pp_lnw = (const float*)d_in[18];
    const float* pp_lnb = (const float*)d_in[19];
    const float* pr_w0 = (const float*)d_in[20];
    const float* pr_b0 = (const float*)d_in[21];
    const float* pr_w1 = (const float*)d_in[22];
    const float* pr_b1 = (const float*)d_in[23];
    float* out = (float*)d_out;

    const int dsm_bytes = 51328 * 4;  // ~200.5 KB
    cudaFuncSetAttribute(rel_fused_tc, cudaFuncAttributeMaxDynamicSharedMemorySize, dsm_bytes);

    prep_kernel<<<2, 256>>>(re_w1, rp_w);
    encode_all<<<256, 128>>>(attrs, states, re_w0, re_b0, oe_w0, oe_b0, oe_w1, oe_b1, rp_w, rp_b);
    rel_fused_tc<<<512, 512, dsm_bytes>>>(rel_attrs, re_w0, re_b1, rp_lnw, rp_lnb);
    obj_update_rs<<<512, 128>>>(pp_w, pp_b, pp_lnw, pp_lnb, rp_w, rp_b);
    final_fused<<<512, 128>>>(rp_lnw, rp_lnb, pp_w, pp_b, pp_lnw, pp_lnb,
                              pr_w0, pr_b0, pr_w1, pr_b1, out);
}

// round 11
// speedup vs baseline: 1.1086x; 1.1086x over previous
#include <cuda_runtime.h>
#include <stdint.h>
#include <math.h>

// B=32, N=64, ATTR=4, STATE=8, REL=4, GDIM=32, NF=128, pstep=2
#define NNODES 2048

// ---------------- scratch (static device memory) ----------------
__device__ float g_E[2048 * 64 * 128];     // E = W_rel @ rel_encode, [bi][j][f] (64 MB)
__device__ float g_obj[2048 * 128];
__device__ float g_u[2048 * 128];
__device__ float g_vt[32 * 128 * 64];      // [b][k][n]
__device__ float g_R[2048 * 128];
__device__ float g_S[2048 * 128];
__device__ float g_agg[2048 * 128];
__device__ float g_w1k[128 * 128];         // re_w1 [f][k], tf32-rounded
__device__ float g_wrk[128 * 128];         // rp_w rel-block [f][k], tf32-rounded

__device__ __forceinline__ float to_tf32(float x) {
    float r;
    asm("cvt.rna.tf32.f32 %0, %1;" : "=f"(r) : "f"(x));
    return r;
}

#define LDSM_X4(r, addr)                                                      \
    asm volatile("ldmatrix.sync.aligned.m8n8.x4.shared.b16 {%0,%1,%2,%3}, [%4];" \
                 : "=r"((r)[0]), "=r"((r)[1]), "=r"((r)[2]), "=r"((r)[3])     \
                 : "r"(addr))

#define MMA_TF32(d, a, b0v, b1v)                                              \
    asm volatile(                                                             \
        "mma.sync.aligned.m16n8k8.row.col.f32.tf32.tf32.f32 "                 \
        "{%0,%1,%2,%3}, {%4,%5,%6,%7}, {%8,%9}, {%0,%1,%2,%3};"               \
        : "+f"((d)[0]), "+f"((d)[1]), "+f"((d)[2]), "+f"((d)[3])              \
        : "r"((a)[0]), "r"((a)[1]), "r"((a)[2]), "r"((a)[3]),                 \
          "r"(b0v), "r"(b1v))

// ---------------- weight prep: tf32 rounding of the two MMA weights ----------------
__global__ void prep_kernel(const float* __restrict__ re_w1,
                            const float* __restrict__ rp_w) {
    int m = blockIdx.x;
    int t = threadIdx.x;
    if (m == 0) {
        for (int i = t; i < 128 * 128; i += 256) g_w1k[i] = to_tf32(re_w1[i]);
    } else {
        for (int i = t; i < 128 * 128; i += 256) {
            int f = i >> 7, k = i & 127;
            g_wrk[i] = to_tf32(rp_w[f * 384 + k]);
        }
    }
}

// ---------------- fused node_pre + obj_encode + rs(step0): 8 nodes/block ----------------
__global__ __launch_bounds__(128) void encode_all(const float* __restrict__ attrs,
                                                  const float* __restrict__ states,
                                                  const float* __restrict__ re_w0,
                                                  const float* __restrict__ re_b0,
                                                  const float* __restrict__ oe_w0,
                                                  const float* __restrict__ oe_b0,
                                                  const float* __restrict__ oe_w1,
                                                  const float* __restrict__ oe_b1,
                                                  const float* __restrict__ rp_w,
                                                  const float* __restrict__ rp_b) {
    __shared__ float sa[8][4];
    __shared__ float ssm[8][8];
    __shared__ float Hs1[8][128];
    __shared__ float Os[8][128];
    int base = blockIdx.x * 8;
    int f = threadIdx.x;
    if (f < 32) {
        int n = f >> 2, c = f & 3;
        sa[n][c] = attrs[(base + n) * 4 + c];
    } else if (f < 96) {
        int q = f - 32;
        int n = q >> 3, c = q & 7;
        ssm[n][c] = states[(base + n) * 8 + c];
    }
    __syncthreads();
    // ---- node_pre ----
    {
        const float* w = re_w0 + f * 20;
        float ws[8], wr4[4], ws4[4];
#pragma unroll
        for (int c = 0; c < 8; c++) ws[c] = w[4 + c];
#pragma unroll
        for (int c = 0; c < 4; c++) { wr4[c] = w[12 + c]; ws4[c] = w[16 + c]; }
        float b0 = re_b0[f];
        int b = base >> 6;
#pragma unroll
        for (int n = 0; n < 8; n++) {
            float u = b0, v = 0.f;
#pragma unroll
            for (int c = 0; c < 8; c++) {
                u += ws[c] * ssm[n][c];
                v -= ws[c] * ssm[n][c];
            }
#pragma unroll
            for (int c = 0; c < 4; c++) {
                u += wr4[c] * sa[n][c];
                v += ws4[c] * sa[n][c];
            }
            int node = base + n;
            g_u[node * 128 + f] = u;
            g_vt[(b * 128 + f) * 64 + (node & 63)] = v;
        }
    }
    // ---- obj encoder layer0 ----
    {
        float w0r[12];
#pragma unroll
        for (int c = 0; c < 12; c++) w0r[c] = oe_w0[f * 12 + c];
        float b0 = oe_b0[f];
#pragma unroll
        for (int n = 0; n < 8; n++) {
            float h = b0;
#pragma unroll
            for (int c = 0; c < 4; c++) h += w0r[c] * sa[n][c];
#pragma unroll
            for (int c = 0; c < 8; c++) h += w0r[4 + c] * ssm[n][c];
            Hs1[n][f] = fmaxf(h, 0.f);
        }
    }
    __syncthreads();
    // ---- obj encoder layer1 ----
    {
        float acc[8] = {0, 0, 0, 0, 0, 0, 0, 0};
#pragma unroll 4
        for (int k = 0; k < 128; k += 4) {
            float4 w = *(const float4*)&oe_w1[f * 128 + k];
#pragma unroll
            for (int n = 0; n < 8; n++) {
                float4 x = *(const float4*)&Hs1[n][k];
                acc[n] += w.x * x.x + w.y * x.y + w.z * x.z + w.w * x.w;
            }
        }
        float b1 = oe_b1[f];
#pragma unroll
        for (int n = 0; n < 8; n++) {
            float o = fmaxf(acc[n] + b1, 0.f);
            Os[n][f] = o;
            g_obj[(base + n) * 128 + f] = o;
        }
    }
    __syncthreads();
    // ---- rs step 0 ----
    {
        float r[8] = {0, 0, 0, 0, 0, 0, 0, 0};
        float s[8] = {0, 0, 0, 0, 0, 0, 0, 0};
        const float* wrow = rp_w + f * 384;
#pragma unroll 4
        for (int k = 0; k < 128; k += 4) {
            float4 wr = *(const float4*)&wrow[128 + k];
            float4 ws = *(const float4*)&wrow[256 + k];
#pragma unroll
            for (int n = 0; n < 8; n++) {
                float4 o = *(const float4*)&Os[n][k];
                r[n] += wr.x * o.x + wr.y * o.y + wr.z * o.z + wr.w * o.w;
                s[n] += ws.x * o.x + ws.y * o.y + ws.z * o.z + ws.w * o.w;
            }
        }
        float bb = rp_b[f];
#pragma unroll
        for (int n = 0; n < 8; n++) {
            g_R[(base + n) * 128 + f] = r[n] + bb;
            g_S[(base + n) * 128 + f] = s[n];
        }
    }
}

// ---------------- fused rel encoder + edge-GEMM + edge-apply(step0) ----------------
__global__ __launch_bounds__(512) void rel_fused_tc(const float* __restrict__ rel_attrs,
                                                    const float* __restrict__ re_w0,
                                                    const float* __restrict__ re_b1,
                                                    const float* __restrict__ rp_lnw,
                                                    const float* __restrict__ rp_lnb) {
    extern __shared__ float dsm[];
    float* Hs = dsm;                    // 256 x 132
    float* Wsm = dsm + 33792;           // 128 x 132
    float* Us = dsm + 50688;            // 4 x 128 (reused as Rs in edge-apply)
    float* Bs = dsm + 51200;            // 128
    int bi0 = blockIdx.x * 4;
    int tid = threadIdx.x;
    int b = bi0 >> 6;
    int lane = tid & 31, warp = tid >> 5;
    int jg = warp >> 1;
    int ng = warp & 1;
    uint32_t hs_base = (uint32_t)__cvta_generic_to_shared(Hs);
    uint32_t w_base = (uint32_t)__cvta_generic_to_shared(Wsm);

    Us[tid] = g_u[(bi0 + (tid >> 7)) * 128 + (tid & 127)];
    if (tid < 128) Bs[tid] = re_b1[tid];
#pragma unroll 4
    for (int i = 0; i < 8; i++) {
        int idx = (i * 512 + tid) * 4;
        float4 v = *(const float4*)&g_w1k[idx];
        *(float4*)&Wsm[(idx >> 7) * 132 + (idx & 127)] = v;
    }
    __syncthreads();

    // ---- build H[r][k] (tf32) ----
    {
        int bi_l = tid >> 7;
        int j = (tid >> 1) & 63;
        int kh = tid & 1;
        float4 rv = *(const float4*)(rel_attrs + ((bi0 + bi_l) * 64 + j) * 4);
        const float* vt = g_vt + b * 8192 + j;
        const float* uu = Us + bi_l * 128;
        float* hrow = Hs + (bi_l * 64 + j) * 132;
#pragma unroll 4
        for (int kk = 0; kk < 64; kk++) {
            int k = kh * 64 + kk;
            const float* w = re_w0 + k * 20;
            float val = uu[k] + vt[k * 64] + rv.x * w[0] + rv.y * w[1] + rv.z * w[2] + rv.w * w[3];
            hrow[k] = to_tf32(fmaxf(val, 0.f));
        }
    }
    __syncthreads();

    uint32_t aAddr = hs_base + 4 * ((32 * jg + (lane & 15)) * 132 + 4 * (lane >> 4));
    uint32_t bAddr = w_base + 4 * ((64 * ng + (lane & 7)) * 132 + 4 * (lane >> 3));
    float d[2][8][4];

    // ================= GEMM1 =================
#pragma unroll
    for (int m = 0; m < 2; m++)
#pragma unroll
        for (int n = 0; n < 8; n++)
#pragma unroll
            for (int q = 0; q < 4; q++) d[m][n][q] = 0.f;
#pragma unroll
    for (int c = 0; c < 8; c++) {
        int k0 = c * 16;
        uint32_t a[2][2][4];
#pragma unroll
        for (int m = 0; m < 2; m++)
#pragma unroll
            for (int s = 0; s < 2; s++)
                LDSM_X4(a[m][s], aAddr + 4 * (m * 16 * 132 + k0 + 8 * s));
#pragma unroll
        for (int h = 0; h < 2; h++) {
            uint32_t bb[4][4];
#pragma unroll
            for (int n4 = 0; n4 < 4; n4++)
                LDSM_X4(bb[n4], bAddr + 4 * ((h * 4 + n4) * 8 * 132 + k0));
#pragma unroll
            for (int s = 0; s < 2; s++)
#pragma unroll
                for (int n4 = 0; n4 < 4; n4++) {
                    MMA_TF32(d[0][h * 4 + n4], a[0][s], bb[n4][2 * s], bb[n4][2 * s + 1]);
                    MMA_TF32(d[1][h * 4 + n4], a[1][s], bb[n4][2 * s], bb[n4][2 * s + 1]);
                }
        }
    }
    __syncthreads();

    // epilogue 1
#pragma unroll
    for (int m = 0; m < 2; m++) {
        int r0 = 32 * jg + 16 * m + (lane >> 2);
#pragma unroll
        for (int n = 0; n < 8; n++) {
            int f0 = 64 * ng + 8 * n + 2 * (lane & 3);
            float bb0 = Bs[f0], bb1 = Bs[f0 + 1];
            Hs[r0 * 132 + f0]           = to_tf32(fmaxf(d[m][n][0] + bb0, 0.f));
            Hs[r0 * 132 + f0 + 1]       = to_tf32(fmaxf(d[m][n][1] + bb1, 0.f));
            Hs[(r0 + 8) * 132 + f0]     = to_tf32(fmaxf(d[m][n][2] + bb0, 0.f));
            Hs[(r0 + 8) * 132 + f0 + 1] = to_tf32(fmaxf(d[m][n][3] + bb1, 0.f));
        }
    }
#pragma unroll 4
    for (int i = 0; i < 8; i++) {
        int idx = (i * 512 + tid) * 4;
        float4 v = *(const float4*)&g_wrk[idx];
        *(float4*)&Wsm[(idx >> 7) * 132 + (idx & 127)] = v;
    }
    __syncthreads();

    // ================= GEMM2 =================
#pragma unroll
    for (int m = 0; m < 2; m++)
#pragma unroll
        for (int n = 0; n < 8; n++)
#pragma unroll
            for (int q = 0; q < 4; q++) d[m][n][q] = 0.f;
#pragma unroll
    for (int c = 0; c < 8; c++) {
        int k0 = c * 16;
        uint32_t a[2][2][4];
#pragma unroll
        for (int m = 0; m < 2; m++)
#pragma unroll
            for (int s = 0; s < 2; s++)
                LDSM_X4(a[m][s], aAddr + 4 * (m * 16 * 132 + k0 + 8 * s));
#pragma unroll
        for (int h = 0; h < 2; h++) {
            uint32_t bb[4][4];
#pragma unroll
            for (int n4 = 0; n4 < 4; n4++)
                LDSM_X4(bb[n4], bAddr + 4 * ((h * 4 + n4) * 8 * 132 + k0));
#pragma unroll
            for (int s = 0; s < 2; s++)
#pragma unroll
                for (int n4 = 0; n4 < 4; n4++) {
                    MMA_TF32(d[0][h * 4 + n4], a[0][s], bb[n4][2 * s], bb[n4][2 * s + 1]);
                    MMA_TF32(d[1][h * 4 + n4], a[1][s], bb[n4][2 * s], bb[n4][2 * s + 1]);
                }
        }
    }
    __syncthreads();

    // epilogue 2: store E to gmem AND into Hs
    float* Ep = g_E + (long)bi0 * 8192;
#pragma unroll
    for (int m = 0; m < 2; m++) {
        int r0 = 32 * jg + 16 * m + (lane >> 2);
#pragma unroll
        for (int n = 0; n < 8; n++) {
            int f0 = 64 * ng + 8 * n + 2 * (lane & 3);
            *(float2*)&Ep[r0 * 128 + f0] = make_float2(d[m][n][0], d[m][n][1]);
            *(float2*)&Ep[(r0 + 8) * 128 + f0] = make_float2(d[m][n][2], d[m][n][3]);
            *(float2*)&Hs[r0 * 132 + f0] = make_float2(d[m][n][0], d[m][n][1]);
            *(float2*)&Hs[(r0 + 8) * 132 + f0] = make_float2(d[m][n][2], d[m][n][3]);
        }
    }
    float* Ss = Wsm;            // 8192 floats
    float* Ps = Wsm + 8192;     // 2048 floats
#pragma unroll
    for (int i = 0; i < 4; i++) {
        int idx4 = (i * 512 + tid) * 4;
        *(float4*)&Ss[idx4] = *(const float4*)&g_S[b * 8192 + idx4];
    }
    Us[tid] = g_R[bi0 * 128 + tid];
    __syncthreads();

    // ---- fused edge-apply step 0 ----
    {
        int bi_l = warp >> 2;
        float4 rv = *(const float4*)&Us[bi_l * 128 + lane * 4];
        float4 lw = *(const float4*)&rp_lnw[lane * 4];
        float4 lb = *(const float4*)&rp_lnb[lane * 4];
        float ag0 = 0.f, ag1 = 0.f, ag2 = 0.f, ag3 = 0.f;
#pragma unroll 4
        for (int rr = 0; rr < 16; rr++) {
            int r = warp * 16 + rr;
            int j = r & 63;
            float4 e = *(const float4*)&Hs[r * 132 + lane * 4];
            float4 sv = *(const float4*)&Ss[j * 128 + lane * 4];
            float4 y = make_float4(e.x + rv.x + sv.x, e.y + rv.y + sv.y,
                                   e.z + rv.z + sv.z, e.w + rv.w + sv.w);
            float s = y.x + y.y + y.z + y.w;
            float ss = y.x * y.x + y.y * y.y + y.z * y.z + y.w * y.w;
#pragma unroll
            for (int off = 16; off; off >>= 1) {
                s += __shfl_xor_sync(0xffffffffu, s, off);
                ss += __shfl_xor_sync(0xffffffffu, ss, off);
            }
            float mu = s * 0.0078125f;
            float var = ss * 0.0078125f - mu * mu;
            float rstd = rsqrtf(var + 1e-5f);
            ag0 += fmaxf((y.x - mu) * rstd * lw.x + lb.x, 0.f);
            ag1 += fmaxf((y.y - mu) * rstd * lw.y + lb.y, 0.f);
            ag2 += fmaxf((y.z - mu) * rstd * lw.z + lb.z, 0.f);
            ag3 += fmaxf((y.w - mu) * rstd * lw.w + lb.w, 0.f);
        }
        *(float4*)&Ps[warp * 128 + lane * 4] = make_float4(ag0, ag1, ag2, ag3);
    }
    __syncthreads();
    {
        int bi_l = tid >> 7, f = tid & 127;
        g_agg[(bi0 + bi_l) * 128 + f] =
            Ps[(4 * bi_l) * 128 + f] + Ps[(4 * bi_l + 1) * 128 + f] +
            Ps[(4 * bi_l + 2) * 128 + f] + Ps[(4 * bi_l + 3) * 128 + f];
    }
}

// ---------------- edge apply (step 1) ----------------
__global__ __launch_bounds__(128) void edge_apply_kernel(const float* __restrict__ rp_lnw,
                                                         const float* __restrict__ rp_lnb) {
    __shared__ float Rs[128];
    __shared__ float Ps[512];
    int bi = blockIdx.x;
    int tid = threadIdx.x;
    int b = bi >> 6;
    int warp = tid >> 5, lane = tid & 31;
    Rs[tid] = g_R[bi * 128 + tid];
    __syncthreads();
    float4 rv = *(const float4*)&Rs[lane * 4];
    float4 lw = *(const float4*)&rp_lnw[lane * 4];
    float4 lb = *(const float4*)&rp_lnb[lane * 4];
    const float* Ep = g_E + (long)bi * 8192;
    float ag0 = 0.f, ag1 = 0.f, ag2 = 0.f, ag3 = 0.f;
#pragma unroll 4
    for (int r = 0; r < 16; r++) {
        int j = warp * 16 + r;
        float4 e = *(const float4*)&Ep[j * 128 + lane * 4];
        float4 sv = *(const float4*)&g_S[(b * 64 + j) * 128 + lane * 4];
        float4 y = make_float4(e.x + rv.x + sv.x, e.y + rv.y + sv.y,
                               e.z + rv.z + sv.z, e.w + rv.w + sv.w);
        float s = y.x + y.y + y.z + y.w;
        float ss = y.x * y.x + y.y * y.y + y.z * y.z + y.w * y.w;
#pragma unroll
        for (int off = 16; off; off >>= 1) {
            s += __shfl_xor_sync(0xffffffffu, s, off);
            ss += __shfl_xor_sync(0xffffffffu, ss, off);
        }
        float mu = s * 0.0078125f;
        float var = ss * 0.0078125f - mu * mu;
        float rstd = rsqrtf(var + 1e-5f);
        ag0 += fmaxf((y.x - mu) * rstd * lw.x + lb.x, 0.f);
        ag1 += fmaxf((y.y - mu) * rstd * lw.y + lb.y, 0.f);
        ag2 += fmaxf((y.z - mu) * rstd * lw.z + lb.z, 0.f);
        ag3 += fmaxf((y.w - mu) * rstd * lw.w + lb.w, 0.f);
    }
    *(float4*)&Ps[warp * 128 + lane * 4] = make_float4(ag0, ag1, ag2, ag3);
    __syncthreads();
    g_agg[bi * 128 + tid] = Ps[tid] + Ps[128 + tid] + Ps[256 + tid] + Ps[384 + tid];
}

// ---------------- fused object update (+rs or +predict): 16 nodes/block, grid 128 ----------------
__global__ __launch_bounds__(128) void obj_update_f(const float* __restrict__ pp_w,
                                                    const float* __restrict__ pp_b,
                                                    const float* __restrict__ pp_lnw,
                                                    const float* __restrict__ pp_lnb,
                                                    const float* __restrict__ rp_w,
                                                    const float* __restrict__ rp_b,
                                                    const float* __restrict__ pr_w0,
                                                    const float* __restrict__ pr_b0,
                                                    const float* __restrict__ pr_w1,
                                                    const float* __restrict__ pr_b1,
                                                    float* __restrict__ out,
                                                    int mode) {  // 0: +rs, 1: +predict
    __shared__ float Xs[16][256];
    __shared__ float Cs[16][132];
    __shared__ float Os2[16][128];
    __shared__ float Hs2[16][128];
    int base = blockIdx.x * 16;
    int f = threadIdx.x;
#pragma unroll
    for (int n = 0; n < 16; n++) {
        Xs[n][f] = g_obj[(base + n) * 128 + f];
        Xs[n][128 + f] = g_agg[(base + n) * 128 + f];
    }
    __syncthreads();
    {
        float acc[16];
#pragma unroll
        for (int n = 0; n < 16; n++) acc[n] = 0.f;
        const float* wrow = pp_w + f * 256;
#pragma unroll 2
        for (int k = 0; k < 256; k += 4) {
            float4 w = *(const float4*)&wrow[k];
#pragma unroll
            for (int n = 0; n < 16; n++) {
                float4 x = *(const float4*)&Xs[n][k];
                acc[n] += w.x * x.x + w.y * x.y + w.z * x.z + w.w * x.w;
            }
        }
        float bb = pp_b[f];
#pragma unroll
        for (int n = 0; n < 16; n++) Cs[n][f] = acc[n] + bb;
    }
    __syncthreads();
    {
        int warp = f >> 5, lane = f & 31;
        float4 lw = *(const float4*)&pp_lnw[lane * 4];
        float4 lb = *(const float4*)&pp_lnb[lane * 4];
#pragma unroll
        for (int r = 0; r < 4; r++) {
            int n = warp * 4 + r;
            float4 y = *(const float4*)&Cs[n][lane * 4];
            float s = y.x + y.y + y.z + y.w;
            float ss = y.x * y.x + y.y * y.y + y.z * y.z + y.w * y.w;
#pragma unroll
            for (int off = 16; off; off >>= 1) {
                s += __shfl_xor_sync(0xffffffffu, s, off);
                ss += __shfl_xor_sync(0xffffffffu, ss, off);
            }
            float mu = s * 0.0078125f;
            float var = ss * 0.0078125f - mu * mu;
            float rstd = rsqrtf(var + 1e-5f);
            float4 o = make_float4(fmaxf((y.x - mu) * rstd * lw.x + lb.x, 0.f),
                                   fmaxf((y.y - mu) * rstd * lw.y + lb.y, 0.f),
                                   fmaxf((y.z - mu) * rstd * lw.z + lb.z, 0.f),
                                   fmaxf((y.w - mu) * rstd * lw.w + lb.w, 0.f));
            *(float4*)&Os2[n][lane * 4] = o;
            if (mode == 0) *(float4*)&g_obj[(base + n) * 128 + lane * 4] = o;
        }
    }
    __syncthreads();
    if (mode == 0) {
        // ---- rs for next step ----
        float r[16], s2[16];
#pragma unroll
        for (int n = 0; n < 16; n++) { r[n] = 0.f; s2[n] = 0.f; }
        const float* wr_row = rp_w + f * 384;
#pragma unroll 2
        for (int k = 0; k < 128; k += 4) {
            float4 wr = *(const float4*)&wr_row[128 + k];
            float4 ws = *(const float4*)&wr_row[256 + k];
#pragma unroll
            for (int n = 0; n < 16; n++) {
                float4 o = *(const float4*)&Os2[n][k];
                r[n] += wr.x * o.x + wr.y * o.y + wr.z * o.z + wr.w * o.w;
                s2[n] += ws.x * o.x + ws.y * o.y + ws.z * o.z + ws.w * o.w;
            }
        }
        float rb = rp_b[f];
#pragma unroll
        for (int n = 0; n < 16; n++) {
            g_R[(base + n) * 128 + f] = r[n] + rb;
            g_S[(base + n) * 128 + f] = s2[n];
        }
    } else {
        // ---- predict head ----
        float pacc[16];
#pragma unroll
        for (int n = 0; n < 16; n++) pacc[n] = 0.f;
        const float* w0row = pr_w0 + f * 128;
#pragma unroll 2
        for (int k = 0; k < 128; k += 4) {
            float4 w = *(const float4*)&w0row[k];
#pragma unroll
            for (int n = 0; n < 16; n++) {
                float4 x = *(const float4*)&Os2[n][k];
                pacc[n] += w.x * x.x + w.y * x.y + w.z * x.z + w.w * x.w;
            }
        }
        float b0 = pr_b0[f];
#pragma unroll
        for (int n = 0; n < 16; n++) Hs2[n][f] = fmaxf(pacc[n] + b0, 0.f);
        __syncthreads();
        // 16 nodes x 32 outs = 512 outputs, 4 per thread
        int op = f & 31;
        const float* wp = pr_w1 + op * 128;
        float wreg[4];
#pragma unroll
        for (int nn = 0; nn < 4; nn++) {
            int n = (f >> 5) * 4 + nn;
            float a0 = 0.f;
#pragma unroll 2
            for (int k = 0; k < 128; k += 4) {
                float4 x = *(const float4*)&Hs2[n][k];
                float4 w = *(const float4*)&wp[k];
                a0 += w.x * x.x + w.y * x.y + w.z * x.z + w.w * x.w;
            }
            wreg[nn] = a0;
        }
        float bb1 = pr_b1[op];
#pragma unroll
        for (int nn = 0; nn < 4; nn++) {
            int n = (f >> 5) * 4 + nn;
            out[(base + n) * 32 + op] = tanhf(wreg[nn] + bb1);
        }
    }
}

// ---------------- launch ----------------
extern "C" void kernel_launch(void* const* d_in, const int* in_sizes, int n_in,
                              void* d_out, int out_size) {
    const float* attrs     = (const float*)d_in[0];
    const float* states    = (const float*)d_in[1];
    const float* rel_attrs = (const float*)d_in[3];
    const float* oe_w0 = (const float*)d_in[4];
    const float* oe_b0 = (const float*)d_in[5];
    const float* oe_w1 = (const float*)d_in[6];
    const float* oe_b1 = (const float*)d_in[7];
    const float* re_w0 = (const float*)d_in[8];
    const float* re_b0 = (const float*)d_in[9];
    const float* re_w1 = (const float*)d_in[10];
    const float* re_b1 = (const float*)d_in[11];
    const float* rp_w  = (const float*)d_in[12];
    const float* rp_b  = (const float*)d_in[13];
    const float* rp_lnw = (const float*)d_in[14];
    const float* rp_lnb = (const float*)d_in[15];
    const float* pp_w  = (const float*)d_in[16];
    const float* pp_b  = (const float*)d_in[17];
    const float* pp_lnw = (const float*)d_in[18];
    const float* pp_lnb = (const float*)d_in[19];
    const float* pr_w0 = (const float*)d_in[20];
    const float* pr_b0 = (const float*)d_in[21];
    const float* pr_w1 = (const float*)d_in[22];
    const float* pr_b1 = (const float*)d_in[23];
    float* out = (float*)d_out;

    const int dsm_bytes = 51328 * 4;  // ~200.5 KB
    cudaFuncSetAttribute(rel_fused_tc, cudaFuncAttributeMaxDynamicSharedMemorySize, dsm_bytes);

    prep_kernel<<<2, 256>>>(re_w1, rp_w);
    encode_all<<<256, 128>>>(attrs, states, re_w0, re_b0, oe_w0, oe_b0, oe_w1, oe_b1, rp_w, rp_b);
    rel_fused_tc<<<512, 512, dsm_bytes>>>(rel_attrs, re_w0, re_b1, rp_lnw, rp_lnb);
    obj_update_f<<<128, 128>>>(pp_w, pp_b, pp_lnw, pp_lnb, rp_w, rp_b,
                               pr_w0, pr_b0, pr_w1, pr_b1, out, 0);
    edge_apply_kernel<<<NNODES, 128>>>(rp_lnw, rp_lnb);
    obj_update_f<<<128, 128>>>(pp_w, pp_b, pp_lnw, pp_lnb, rp_w, rp_b,
                               pr_w0, pr_b0, pr_w1, pr_b1, out, 1);
}

// round 12
// speedup vs baseline: 1.1903x; 1.0737x over previous
#include <cuda_runtime.h>
#include <stdint.h>
#include <math.h>

// B=32, N=64, ATTR=4, STATE=8, REL=4, GDIM=32, NF=128, pstep=2
#define NNODES 2048

// ---------------- scratch (static device memory) ----------------
__device__ float g_E[2048 * 64 * 128];     // E = W_rel @ rel_encode, [bi][j][f] (64 MB)
__device__ float g_obj[2048 * 128];
__device__ float g_u[2048 * 128];
__device__ float g_vt[32 * 128 * 64];      // [b][k][n]
__device__ float g_R[2048 * 128];
__device__ float g_S[2048 * 128];
__device__ float g_agg[2048 * 128];
__device__ float g_w1k[128 * 128];         // re_w1 [f][k], tf32-rounded
__device__ float g_wrk[128 * 128];         // rp_w rel-block [f][k], tf32-rounded

__device__ __forceinline__ float to_tf32(float x) {
    float r;
    asm("cvt.rna.tf32.f32 %0, %1;" : "=f"(r) : "f"(x));
    return r;
}

#define LDSM_X4(r, addr)                                                      \
    asm volatile("ldmatrix.sync.aligned.m8n8.x4.shared.b16 {%0,%1,%2,%3}, [%4];" \
                 : "=r"((r)[0]), "=r"((r)[1]), "=r"((r)[2]), "=r"((r)[3])     \
                 : "r"(addr))

#define MMA_TF32(d, a, b0v, b1v)                                              \
    asm volatile(                                                             \
        "mma.sync.aligned.m16n8k8.row.col.f32.tf32.tf32.f32 "                 \
        "{%0,%1,%2,%3}, {%4,%5,%6,%7}, {%8,%9}, {%0,%1,%2,%3};"               \
        : "+f"((d)[0]), "+f"((d)[1]), "+f"((d)[2]), "+f"((d)[3])              \
        : "r"((a)[0]), "r"((a)[1]), "r"((a)[2]), "r"((a)[3]),                 \
          "r"(b0v), "r"(b1v))

// ---------------- weight prep ----------------
__global__ void prep_kernel(const float* __restrict__ re_w1,
                            const float* __restrict__ rp_w) {
    int m = blockIdx.x;
    int t = threadIdx.x;
    if (m == 0) {
        for (int i = t; i < 128 * 128; i += 256) g_w1k[i] = to_tf32(re_w1[i]);
    } else {
        for (int i = t; i < 128 * 128; i += 256) {
            int f = i >> 7, k = i & 127;
            g_wrk[i] = to_tf32(rp_w[f * 384 + k]);
        }
    }
}

// ---------------- fused node_pre + obj_encode + rs(step0): 8 nodes/block ----------------
__global__ __launch_bounds__(128) void encode_all(const float* __restrict__ attrs,
                                                  const float* __restrict__ states,
                                                  const float* __restrict__ re_w0,
                                                  const float* __restrict__ re_b0,
                                                  const float* __restrict__ oe_w0,
                                                  const float* __restrict__ oe_b0,
                                                  const float* __restrict__ oe_w1,
                                                  const float* __restrict__ oe_b1,
                                                  const float* __restrict__ rp_w,
                                                  const float* __restrict__ rp_b) {
    __shared__ float sa[8][4];
    __shared__ float ssm[8][8];
    __shared__ float Hs1[8][128];
    __shared__ float Os[8][128];
    int base = blockIdx.x * 8;
    int f = threadIdx.x;
    if (f < 32) {
        int n = f >> 2, c = f & 3;
        sa[n][c] = attrs[(base + n) * 4 + c];
    } else if (f < 96) {
        int q = f - 32;
        int n = q >> 3, c = q & 7;
        ssm[n][c] = states[(base + n) * 8 + c];
    }
    __syncthreads();
    {
        const float* w = re_w0 + f * 20;
        float ws[8], wr4[4], ws4[4];
#pragma unroll
        for (int c = 0; c < 8; c++) ws[c] = w[4 + c];
#pragma unroll
        for (int c = 0; c < 4; c++) { wr4[c] = w[12 + c]; ws4[c] = w[16 + c]; }
        float b0 = re_b0[f];
        int b = base >> 6;
#pragma unroll
        for (int n = 0; n < 8; n++) {
            float u = b0, v = 0.f;
#pragma unroll
            for (int c = 0; c < 8; c++) {
                u += ws[c] * ssm[n][c];
                v -= ws[c] * ssm[n][c];
            }
#pragma unroll
            for (int c = 0; c < 4; c++) {
                u += wr4[c] * sa[n][c];
                v += ws4[c] * sa[n][c];
            }
            int node = base + n;
            g_u[node * 128 + f] = u;
            g_vt[(b * 128 + f) * 64 + (node & 63)] = v;
        }
    }
    {
        float w0r[12];
#pragma unroll
        for (int c = 0; c < 12; c++) w0r[c] = oe_w0[f * 12 + c];
        float b0 = oe_b0[f];
#pragma unroll
        for (int n = 0; n < 8; n++) {
            float h = b0;
#pragma unroll
            for (int c = 0; c < 4; c++) h += w0r[c] * sa[n][c];
#pragma unroll
            for (int c = 0; c < 8; c++) h += w0r[4 + c] * ssm[n][c];
            Hs1[n][f] = fmaxf(h, 0.f);
        }
    }
    __syncthreads();
    {
        float acc[8] = {0, 0, 0, 0, 0, 0, 0, 0};
#pragma unroll 4
        for (int k = 0; k < 128; k += 4) {
            float4 w = *(const float4*)&oe_w1[f * 128 + k];
#pragma unroll
            for (int n = 0; n < 8; n++) {
                float4 x = *(const float4*)&Hs1[n][k];
                acc[n] += w.x * x.x + w.y * x.y + w.z * x.z + w.w * x.w;
            }
        }
        float b1 = oe_b1[f];
#pragma unroll
        for (int n = 0; n < 8; n++) {
            float o = fmaxf(acc[n] + b1, 0.f);
            Os[n][f] = o;
            g_obj[(base + n) * 128 + f] = o;
        }
    }
    __syncthreads();
    {
        float r[8] = {0, 0, 0, 0, 0, 0, 0, 0};
        float s[8] = {0, 0, 0, 0, 0, 0, 0, 0};
        const float* wrow = rp_w + f * 384;
#pragma unroll 4
        for (int k = 0; k < 128; k += 4) {
            float4 wr = *(const float4*)&wrow[128 + k];
            float4 ws = *(const float4*)&wrow[256 + k];
#pragma unroll
            for (int n = 0; n < 8; n++) {
                float4 o = *(const float4*)&Os[n][k];
                r[n] += wr.x * o.x + wr.y * o.y + wr.z * o.z + wr.w * o.w;
                s[n] += ws.x * o.x + ws.y * o.y + ws.z * o.z + ws.w * o.w;
            }
        }
        float bb = rp_b[f];
#pragma unroll
        for (int n = 0; n < 8; n++) {
            g_R[(base + n) * 128 + f] = r[n] + bb;
            g_S[(base + n) * 128 + f] = s[n];
        }
    }
}

// ---------------- fused rel encoder + edge-GEMM + edge-apply(step0) ----------------
__global__ __launch_bounds__(512) void rel_fused_tc(const float* __restrict__ rel_attrs,
                                                    const float* __restrict__ re_w0,
                                                    const float* __restrict__ re_b1,
                                                    const float* __restrict__ rp_lnw,
                                                    const float* __restrict__ rp_lnb) {
    extern __shared__ float dsm[];
    float* Hs = dsm;                    // 256 x 132
    float* Wsm = dsm + 33792;           // 128 x 132
    float* Us = dsm + 50688;            // 4 x 128
    float* Bs = dsm + 51200;            // 128
    int bi0 = blockIdx.x * 4;
    int tid = threadIdx.x;
    int b = bi0 >> 6;
    int lane = tid & 31, warp = tid >> 5;
    int jg = warp >> 1;
    int ng = warp & 1;
    uint32_t hs_base = (uint32_t)__cvta_generic_to_shared(Hs);
    uint32_t w_base = (uint32_t)__cvta_generic_to_shared(Wsm);

    Us[tid] = g_u[(bi0 + (tid >> 7)) * 128 + (tid & 127)];
    if (tid < 128) Bs[tid] = re_b1[tid];
#pragma unroll 4
    for (int i = 0; i < 8; i++) {
        int idx = (i * 512 + tid) * 4;
        float4 v = *(const float4*)&g_w1k[idx];
        *(float4*)&Wsm[(idx >> 7) * 132 + (idx & 127)] = v;
    }
    __syncthreads();

    {
        int bi_l = tid >> 7;
        int j = (tid >> 1) & 63;
        int kh = tid & 1;
        float4 rv = *(const float4*)(rel_attrs + ((bi0 + bi_l) * 64 + j) * 4);
        const float* vt = g_vt + b * 8192 + j;
        const float* uu = Us + bi_l * 128;
        float* hrow = Hs + (bi_l * 64 + j) * 132;
#pragma unroll 4
        for (int kk = 0; kk < 64; kk++) {
            int k = kh * 64 + kk;
            const float* w = re_w0 + k * 20;
            float val = uu[k] + vt[k * 64] + rv.x * w[0] + rv.y * w[1] + rv.z * w[2] + rv.w * w[3];
            hrow[k] = to_tf32(fmaxf(val, 0.f));
        }
    }
    __syncthreads();

    uint32_t aAddr = hs_base + 4 * ((32 * jg + (lane & 15)) * 132 + 4 * (lane >> 4));
    uint32_t bAddr = w_base + 4 * ((64 * ng + (lane & 7)) * 132 + 4 * (lane >> 3));
    float d[2][8][4];

    // ================= GEMM1 =================
#pragma unroll
    for (int m = 0; m < 2; m++)
#pragma unroll
        for (int n = 0; n < 8; n++)
#pragma unroll
            for (int q = 0; q < 4; q++) d[m][n][q] = 0.f;
#pragma unroll
    for (int c = 0; c < 8; c++) {
        int k0 = c * 16;
        uint32_t a[2][2][4];
#pragma unroll
        for (int m = 0; m < 2; m++)
#pragma unroll
            for (int s = 0; s < 2; s++)
                LDSM_X4(a[m][s], aAddr + 4 * (m * 16 * 132 + k0 + 8 * s));
#pragma unroll
        for (int h = 0; h < 2; h++) {
            uint32_t bb[4][4];
#pragma unroll
            for (int n4 = 0; n4 < 4; n4++)
                LDSM_X4(bb[n4], bAddr + 4 * ((h * 4 + n4) * 8 * 132 + k0));
#pragma unroll
            for (int s = 0; s < 2; s++)
#pragma unroll
                for (int n4 = 0; n4 < 4; n4++) {
                    MMA_TF32(d[0][h * 4 + n4], a[0][s], bb[n4][2 * s], bb[n4][2 * s + 1]);
                    MMA_TF32(d[1][h * 4 + n4], a[1][s], bb[n4][2 * s], bb[n4][2 * s + 1]);
                }
        }
    }
    __syncthreads();

    // epilogue 1
#pragma unroll
    for (int m = 0; m < 2; m++) {
        int r0 = 32 * jg + 16 * m + (lane >> 2);
#pragma unroll
        for (int n = 0; n < 8; n++) {
            int f0 = 64 * ng + 8 * n + 2 * (lane & 3);
            float bb0 = Bs[f0], bb1 = Bs[f0 + 1];
            Hs[r0 * 132 + f0]           = to_tf32(fmaxf(d[m][n][0] + bb0, 0.f));
            Hs[r0 * 132 + f0 + 1]       = to_tf32(fmaxf(d[m][n][1] + bb1, 0.f));
            Hs[(r0 + 8) * 132 + f0]     = to_tf32(fmaxf(d[m][n][2] + bb0, 0.f));
            Hs[(r0 + 8) * 132 + f0 + 1] = to_tf32(fmaxf(d[m][n][3] + bb1, 0.f));
        }
    }
#pragma unroll 4
    for (int i = 0; i < 8; i++) {
        int idx = (i * 512 + tid) * 4;
        float4 v = *(const float4*)&g_wrk[idx];
        *(float4*)&Wsm[(idx >> 7) * 132 + (idx & 127)] = v;
    }
    __syncthreads();

    // ================= GEMM2 =================
#pragma unroll
    for (int m = 0; m < 2; m++)
#pragma unroll
        for (int n = 0; n < 8; n++)
#pragma unroll
            for (int q = 0; q < 4; q++) d[m][n][q] = 0.f;
#pragma unroll
    for (int c = 0; c < 8; c++) {
        int k0 = c * 16;
        uint32_t a[2][2][4];
#pragma unroll
        for (int m = 0; m < 2; m++)
#pragma unroll
            for (int s = 0; s < 2; s++)
                LDSM_X4(a[m][s], aAddr + 4 * (m * 16 * 132 + k0 + 8 * s));
#pragma unroll
        for (int h = 0; h < 2; h++) {
            uint32_t bb[4][4];
#pragma unroll
            for (int n4 = 0; n4 < 4; n4++)
                LDSM_X4(bb[n4], bAddr + 4 * ((h * 4 + n4) * 8 * 132 + k0));
#pragma unroll
            for (int s = 0; s < 2; s++)
#pragma unroll
                for (int n4 = 0; n4 < 4; n4++) {
                    MMA_TF32(d[0][h * 4 + n4], a[0][s], bb[n4][2 * s], bb[n4][2 * s + 1]);
                    MMA_TF32(d[1][h * 4 + n4], a[1][s], bb[n4][2 * s], bb[n4][2 * s + 1]);
                }
        }
    }
    __syncthreads();

    // epilogue 2
    float* Ep = g_E + (long)bi0 * 8192;
#pragma unroll
    for (int m = 0; m < 2; m++) {
        int r0 = 32 * jg + 16 * m + (lane >> 2);
#pragma unroll
        for (int n = 0; n < 8; n++) {
            int f0 = 64 * ng + 8 * n + 2 * (lane & 3);
            *(float2*)&Ep[r0 * 128 + f0] = make_float2(d[m][n][0], d[m][n][1]);
            *(float2*)&Ep[(r0 + 8) * 128 + f0] = make_float2(d[m][n][2], d[m][n][3]);
            *(float2*)&Hs[r0 * 132 + f0] = make_float2(d[m][n][0], d[m][n][1]);
            *(float2*)&Hs[(r0 + 8) * 132 + f0] = make_float2(d[m][n][2], d[m][n][3]);
        }
    }
    float* Ss = Wsm;
    float* Ps = Wsm + 8192;
#pragma unroll
    for (int i = 0; i < 4; i++) {
        int idx4 = (i * 512 + tid) * 4;
        *(float4*)&Ss[idx4] = *(const float4*)&g_S[b * 8192 + idx4];
    }
    Us[tid] = g_R[bi0 * 128 + tid];
    __syncthreads();

    // ---- fused edge-apply step 0 ----
    {
        int bi_l = warp >> 2;
        float4 rv = *(const float4*)&Us[bi_l * 128 + lane * 4];
        float4 lw = *(const float4*)&rp_lnw[lane * 4];
        float4 lb = *(const float4*)&rp_lnb[lane * 4];
        float ag0 = 0.f, ag1 = 0.f, ag2 = 0.f, ag3 = 0.f;
#pragma unroll 4
        for (int rr = 0; rr < 16; rr++) {
            int r = warp * 16 + rr;
            int j = r & 63;
            float4 e = *(const float4*)&Hs[r * 132 + lane * 4];
            float4 sv = *(const float4*)&Ss[j * 128 + lane * 4];
            float4 y = make_float4(e.x + rv.x + sv.x, e.y + rv.y + sv.y,
                                   e.z + rv.z + sv.z, e.w + rv.w + sv.w);
            float s = y.x + y.y + y.z + y.w;
            float ss = y.x * y.x + y.y * y.y + y.z * y.z + y.w * y.w;
#pragma unroll
            for (int off = 16; off; off >>= 1) {
                s += __shfl_xor_sync(0xffffffffu, s, off);
                ss += __shfl_xor_sync(0xffffffffu, ss, off);
            }
            float mu = s * 0.0078125f;
            float var = ss * 0.0078125f - mu * mu;
            float rstd = rsqrtf(var + 1e-5f);
            ag0 += fmaxf((y.x - mu) * rstd * lw.x + lb.x, 0.f);
            ag1 += fmaxf((y.y - mu) * rstd * lw.y + lb.y, 0.f);
            ag2 += fmaxf((y.z - mu) * rstd * lw.z + lb.z, 0.f);
            ag3 += fmaxf((y.w - mu) * rstd * lw.w + lb.w, 0.f);
        }
        *(float4*)&Ps[warp * 128 + lane * 4] = make_float4(ag0, ag1, ag2, ag3);
    }
    __syncthreads();
    {
        int bi_l = tid >> 7, f = tid & 127;
        g_agg[(bi0 + bi_l) * 128 + f] =
            Ps[(4 * bi_l) * 128 + f] + Ps[(4 * bi_l + 1) * 128 + f] +
            Ps[(4 * bi_l + 2) * 128 + f] + Ps[(4 * bi_l + 3) * 128 + f];
    }
}

// ---------------- edge apply (step 1) ----------------
__global__ __launch_bounds__(128) void edge_apply_kernel(const float* __restrict__ rp_lnw,
                                                         const float* __restrict__ rp_lnb) {
    __shared__ float Rs[128];
    __shared__ float Ps[512];
    int bi = blockIdx.x;
    int tid = threadIdx.x;
    int b = bi >> 6;
    int warp = tid >> 5, lane = tid & 31;
    Rs[tid] = g_R[bi * 128 + tid];
    __syncthreads();
    float4 rv = *(const float4*)&Rs[lane * 4];
    float4 lw = *(const float4*)&rp_lnw[lane * 4];
    float4 lb = *(const float4*)&rp_lnb[lane * 4];
    const float* Ep = g_E + (long)bi * 8192;
    float ag0 = 0.f, ag1 = 0.f, ag2 = 0.f, ag3 = 0.f;
#pragma unroll 4
    for (int r = 0; r < 16; r++) {
        int j = warp * 16 + r;
        float4 e = *(const float4*)&Ep[j * 128 + lane * 4];
        float4 sv = *(const float4*)&g_S[(b * 64 + j) * 128 + lane * 4];
        float4 y = make_float4(e.x + rv.x + sv.x, e.y + rv.y + sv.y,
                               e.z + rv.z + sv.z, e.w + rv.w + sv.w);
        float s = y.x + y.y + y.z + y.w;
        float ss = y.x * y.x + y.y * y.y + y.z * y.z + y.w * y.w;
#pragma unroll
        for (int off = 16; off; off >>= 1) {
            s += __shfl_xor_sync(0xffffffffu, s, off);
            ss += __shfl_xor_sync(0xffffffffu, ss, off);
        }
        float mu = s * 0.0078125f;
        float var = ss * 0.0078125f - mu * mu;
        float rstd = rsqrtf(var + 1e-5f);
        ag0 += fmaxf((y.x - mu) * rstd * lw.x + lb.x, 0.f);
        ag1 += fmaxf((y.y - mu) * rstd * lw.y + lb.y, 0.f);
        ag2 += fmaxf((y.z - mu) * rstd * lw.z + lb.z, 0.f);
        ag3 += fmaxf((y.w - mu) * rstd * lw.w + lb.w, 0.f);
    }
    *(float4*)&Ps[warp * 128 + lane * 4] = make_float4(ag0, ag1, ag2, ag3);
    __syncthreads();
    g_agg[bi * 128 + tid] = Ps[tid] + Ps[128 + tid] + Ps[256 + tid] + Ps[384 + tid];
}

// ---------------- fused object update (+rs or +predict): 16 nodes/block, 512 thr, k-split ----------------
__global__ __launch_bounds__(512) void obj_update_f(const float* __restrict__ pp_w,
                                                    const float* __restrict__ pp_b,
                                                    const float* __restrict__ pp_lnw,
                                                    const float* __restrict__ pp_lnb,
                                                    const float* __restrict__ rp_w,
                                                    const float* __restrict__ rp_b,
                                                    const float* __restrict__ pr_w0,
                                                    const float* __restrict__ pr_b0,
                                                    const float* __restrict__ pr_w1,
                                                    const float* __restrict__ pr_b1,
                                                    float* __restrict__ out,
                                                    int mode) {  // 0: +rs, 1: +predict
    extern __shared__ float sm[];
    float* Xs   = sm;            // [16][256]  = 4096
    float* part = sm + 4096;     // 8192 (partials, reused)
    float* Cs   = sm + 12288;    // [16][128]  = 2048
    float* Os2  = sm + 14336;    // [16][128]  = 2048
    float* Hs2  = sm + 16384;    // [16][128]  = 2048
    int base = blockIdx.x * 16;
    int tid = threadIdx.x;
    int warp = tid >> 5, lane = tid & 31;

#pragma unroll
    for (int i = 0; i < 8; i++) {
        int idx = i * 512 + tid;
        int n = idx >> 8, c = idx & 255;
        Xs[idx] = (c < 128) ? g_obj[(base + n) * 128 + c]
                            : g_agg[(base + n) * 128 + (c - 128)];
    }
    __syncthreads();

    // ---- phase 1: pp GEMV, 4-way k-split ----
    {
        int f = tid & 127, q = tid >> 7;
        float acc[16];
#pragma unroll
        for (int n = 0; n < 16; n++) acc[n] = 0.f;
        const float* wrow = pp_w + f * 256 + q * 64;
        const float* xb = Xs + q * 64;
#pragma unroll 4
        for (int k = 0; k < 64; k += 4) {
            float4 w = *(const float4*)&wrow[k];
#pragma unroll
            for (int n = 0; n < 16; n++) {
                float4 x = *(const float4*)&xb[n * 256 + k];
                acc[n] += w.x * x.x + w.y * x.y + w.z * x.z + w.w * x.w;
            }
        }
#pragma unroll
        for (int n = 0; n < 16; n++) part[q * 2048 + n * 128 + f] = acc[n];
    }
    __syncthreads();
#pragma unroll
    for (int i = 0; i < 4; i++) {
        int idx = i * 512 + tid;   // 2048 outputs: n = idx>>7, f = idx&127
        float v = part[idx] + part[2048 + idx] + part[4096 + idx] + part[6144 + idx];
        Cs[idx] = v + pp_b[idx & 127];
    }
    __syncthreads();

    // ---- phase 2: LN, one warp per node ----
    {
        float4 lw = *(const float4*)&pp_lnw[lane * 4];
        float4 lb = *(const float4*)&pp_lnb[lane * 4];
        int n = warp;
        float4 y = *(const float4*)&Cs[n * 128 + lane * 4];
        float s = y.x + y.y + y.z + y.w;
        float ss = y.x * y.x + y.y * y.y + y.z * y.z + y.w * y.w;
#pragma unroll
        for (int off = 16; off; off >>= 1) {
            s += __shfl_xor_sync(0xffffffffu, s, off);
            ss += __shfl_xor_sync(0xffffffffu, ss, off);
        }
        float mu = s * 0.0078125f;
        float var = ss * 0.0078125f - mu * mu;
        float rstd = rsqrtf(var + 1e-5f);
        float4 o = make_float4(fmaxf((y.x - mu) * rstd * lw.x + lb.x, 0.f),
                               fmaxf((y.y - mu) * rstd * lw.y + lb.y, 0.f),
                               fmaxf((y.z - mu) * rstd * lw.z + lb.z, 0.f),
                               fmaxf((y.w - mu) * rstd * lw.w + lb.w, 0.f));
        *(float4*)&Os2[n * 128 + lane * 4] = o;
        if (mode == 0) *(float4*)&g_obj[(base + n) * 128 + lane * 4] = o;
    }
    __syncthreads();

    if (mode == 0) {
        // ---- rs: 256 outputs/node (R|S), 2-way k-split ----
        int fo = tid & 255, q = tid >> 8;
        float acc[16];
#pragma unroll
        for (int n = 0; n < 16; n++) acc[n] = 0.f;
        const float* wrow = (fo < 128) ? (rp_w + fo * 384 + 128 + q * 64)
                                       : (rp_w + (fo - 128) * 384 + 256 + q * 64);
        const float* ob = Os2 + q * 64;
#pragma unroll 4
        for (int k = 0; k < 64; k += 4) {
            float4 w = *(const float4*)&wrow[k];
#pragma unroll
            for (int n = 0; n < 16; n++) {
                float4 x = *(const float4*)&ob[n * 128 + k];
                acc[n] += w.x * x.x + w.y * x.y + w.z * x.z + w.w * x.w;
            }
        }
#pragma unroll
        for (int n = 0; n < 16; n++) part[q * 4096 + n * 256 + fo] = acc[n];
        __syncthreads();
#pragma unroll
        for (int i = 0; i < 8; i++) {
            int idx = i * 512 + tid;  // 4096 outputs: n = idx>>8, fo = idx&255
            float v = part[idx] + part[4096 + idx];
            int n = idx >> 8, fo2 = idx & 255;
            if (fo2 < 128) g_R[(base + n) * 128 + fo2] = v + rp_b[fo2];
            else g_S[(base + n) * 128 + fo2 - 128] = v;
        }
    } else {
        // ---- predict layer1: 4-way k-split ----
        {
            int f = tid & 127, q = tid >> 7;
            float acc[16];
#pragma unroll
            for (int n = 0; n < 16; n++) acc[n] = 0.f;
            const float* wrow = pr_w0 + f * 128 + q * 32;
            const float* ob = Os2 + q * 32;
#pragma unroll 4
            for (int k = 0; k < 32; k += 4) {
                float4 w = *(const float4*)&wrow[k];
#pragma unroll
                for (int n = 0; n < 16; n++) {
                    float4 x = *(const float4*)&ob[n * 128 + k];
                    acc[n] += w.x * x.x + w.y * x.y + w.z * x.z + w.w * x.w;
                }
            }
#pragma unroll
            for (int n = 0; n < 16; n++) part[q * 2048 + n * 128 + f] = acc[n];
        }
        __syncthreads();
#pragma unroll
        for (int i = 0; i < 4; i++) {
            int idx = i * 512 + tid;
            float v = part[idx] + part[2048 + idx] + part[4096 + idx] + part[6144 + idx];
            Hs2[idx] = fmaxf(v + pr_b0[idx & 127], 0.f);
        }
        __syncthreads();
        // ---- predict layer2: 512 outputs, one per thread ----
        {
            int n = tid >> 5, op = tid & 31;
            float a0 = 0.f;
            const float* wp = pr_w1 + op * 128;
#pragma unroll 4
            for (int k = 0; k < 128; k += 4) {
                float4 x = *(const float4*)&Hs2[n * 128 + k];
                float4 w = *(const float4*)&wp[k];
                a0 += w.x * x.x + w.y * x.y + w.z * x.z + w.w * x.w;
            }
            out[(base + n) * 32 + op] = tanhf(a0 + pr_b1[op]);
        }
    }
}

// ---------------- launch ----------------
extern "C" void kernel_launch(void* const* d_in, const int* in_sizes, int n_in,
                              void* d_out, int out_size) {
    const float* attrs     = (const float*)d_in[0];
    const float* states    = (const float*)d_in[1];
    const float* rel_attrs = (const float*)d_in[3];
    const float* oe_w0 = (const float*)d_in[4];
    const float* oe_b0 = (const float*)d_in[5];
    const float* oe_w1 = (const float*)d_in[6];
    const float* oe_b1 = (const float*)d_in[7];
    const float* re_w0 = (const float*)d_in[8];
    const float* re_b0 = (const float*)d_in[9];
    const float* re_w1 = (const float*)d_in[10];
    const float* re_b1 = (const float*)d_in[11];
    const float* rp_w  = (const float*)d_in[12];
    const float* rp_b  = (const float*)d_in[13];
    const float* rp_lnw = (const float*)d_in[14];
    const float* rp_lnb = (const float*)d_in[15];
    const float* pp_w  = (const float*)d_in[16];
    const float* pp_b  = (const float*)d_in[17];
    const float* pp_lnw = (const float*)d_in[18];
    const float* pp_lnb = (const float*)d_in[19];
    const float* pr_w0 = (const float*)d_in[20];
    const float* pr_b0 = (const float*)d_in[21];
    const float* pr_w1 = (const float*)d_in[22];
    const float* pr_b1 = (const float*)d_in[23];
    float* out = (float*)d_out;

    const int dsm_bytes = 51328 * 4;   // rel_fused: ~200.5 KB
    const int ou_bytes  = 18432 * 4;   // obj_update: 72 KB
    cudaFuncSetAttribute(rel_fused_tc, cudaFuncAttributeMaxDynamicSharedMemorySize, dsm_bytes);
    cudaFuncSetAttribute(obj_update_f, cudaFuncAttributeMaxDynamicSharedMemorySize, ou_bytes);

    prep_kernel<<<2, 256>>>(re_w1, rp_w);
    encode_all<<<256, 128>>>(attrs, states, re_w0, re_b0, oe_w0, oe_b0, oe_w1, oe_b1, rp_w, rp_b);
    rel_fused_tc<<<512, 512, dsm_bytes>>>(rel_attrs, re_w0, re_b1, rp_lnw, rp_lnb);
    obj_update_f<<<128, 512, ou_bytes>>>(pp_w, pp_b, pp_lnw, pp_lnb, rp_w, rp_b,
                                         pr_w0, pr_b0, pr_w1, pr_b1, out, 0);
    edge_apply_kernel<<<NNODES, 128>>>(rp_lnw, rp_lnb);
    obj_update_f<<<128, 512, ou_bytes>>>(pp_w, pp_b, pp_lnw, pp_lnb, rp_w, rp_b,
                                         pr_w0, pr_b0, pr_w1, pr_b1, out, 1);
}

// round 14
// speedup vs baseline: 1.4057x; 1.1809x over previous
#include <cuda_runtime.h>
#include <cuda_fp16.h>
#include <stdint.h>
#include <math.h>

// B=32, N=64, ATTR=4, STATE=8, REL=4, GDIM=32, NF=128, pstep=2
#define NNODES 2048

// ---------------- scratch (static device memory) ----------------
__device__ float g_E[2048 * 64 * 128];     // E, [bi][j][f] (64 MB)
__device__ float g_obj[2048 * 128];
__device__ float g_u[2048 * 128];
__device__ float g_vt[32 * 128 * 64];      // [b][k][n]
__device__ float g_R[2048 * 128];
__device__ float g_S[2048 * 128];
__device__ float g_agg[2048 * 128];
__device__ __half g_w1h[128 * 128];        // re_w1 [f][k] fp16
__device__ __half g_wrh[128 * 128];        // rp_w rel-block [f][k] fp16

#define LDSM_X4(r, addr)                                                      \
    asm volatile("ldmatrix.sync.aligned.m8n8.x4.shared.b16 {%0,%1,%2,%3}, [%4];" \
                 : "=r"((r)[0]), "=r"((r)[1]), "=r"((r)[2]), "=r"((r)[3])     \
                 : "r"(addr))

#define MMA_F16(d, a, b0v, b1v)                                               \
    asm volatile(                                                             \
        "mma.sync.aligned.m16n8k16.row.col.f32.f16.f16.f32 "                  \
        "{%0,%1,%2,%3}, {%4,%5,%6,%7}, {%8,%9}, {%0,%1,%2,%3};"               \
        : "+f"((d)[0]), "+f"((d)[1]), "+f"((d)[2]), "+f"((d)[3])              \
        : "r"((a)[0]), "r"((a)[1]), "r"((a)[2]), "r"((a)[3]),                 \
          "r"(b0v), "r"(b1v))

// ---------------- weight prep: fp16 conversion ----------------
__global__ void prep_kernel(const float* __restrict__ re_w1,
                            const float* __restrict__ rp_w) {
    int m = blockIdx.x;
    int t = threadIdx.x;
    if (m == 0) {
        for (int i = t; i < 128 * 128; i += 256) g_w1h[i] = __float2half_rn(re_w1[i]);
    } else {
        for (int i = t; i < 128 * 128; i += 256) {
            int f = i >> 7, k = i & 127;
            g_wrh[i] = __float2half_rn(rp_w[f * 384 + k]);
        }
    }
}

// ---------------- fused node_pre + obj_encode + rs(step0): 8 nodes/block ----------------
__global__ __launch_bounds__(128) void encode_all(const float* __restrict__ attrs,
                                                  const float* __restrict__ states,
                                                  const float* __restrict__ re_w0,
                                                  const float* __restrict__ re_b0,
                                                  const float* __restrict__ oe_w0,
                                                  const float* __restrict__ oe_b0,
                                                  const float* __restrict__ oe_w1,
                                                  const float* __restrict__ oe_b1,
                                                  const float* __restrict__ rp_w,
                                                  const float* __restrict__ rp_b) {
    __shared__ float sa[8][4];
    __shared__ float ssm[8][8];
    __shared__ float Hs1[8][128];
    __shared__ float Os[8][128];
    int base = blockIdx.x * 8;
    int f = threadIdx.x;
    if (f < 32) {
        int n = f >> 2, c = f & 3;
        sa[n][c] = attrs[(base + n) * 4 + c];
    } else if (f < 96) {
        int q = f - 32;
        int n = q >> 3, c = q & 7;
        ssm[n][c] = states[(base + n) * 8 + c];
    }
    __syncthreads();
    {
        const float* w = re_w0 + f * 20;
        float ws[8], wr4[4], ws4[4];
#pragma unroll
        for (int c = 0; c < 8; c++) ws[c] = w[4 + c];
#pragma unroll
        for (int c = 0; c < 4; c++) { wr4[c] = w[12 + c]; ws4[c] = w[16 + c]; }
        float b0 = re_b0[f];
        int b = base >> 6;
#pragma unroll
        for (int n = 0; n < 8; n++) {
            float u = b0, v = 0.f;
#pragma unroll
            for (int c = 0; c < 8; c++) {
                u += ws[c] * ssm[n][c];
                v -= ws[c] * ssm[n][c];
            }
#pragma unroll
            for (int c = 0; c < 4; c++) {
                u += wr4[c] * sa[n][c];
                v += ws4[c] * sa[n][c];
            }
            int node = base + n;
            g_u[node * 128 + f] = u;
            g_vt[(b * 128 + f) * 64 + (node & 63)] = v;
        }
    }
    {
        float w0r[12];
#pragma unroll
        for (int c = 0; c < 12; c++) w0r[c] = oe_w0[f * 12 + c];
        float b0 = oe_b0[f];
#pragma unroll
        for (int n = 0; n < 8; n++) {
            float h = b0;
#pragma unroll
            for (int c = 0; c < 4; c++) h += w0r[c] * sa[n][c];
#pragma unroll
            for (int c = 0; c < 8; c++) h += w0r[4 + c] * ssm[n][c];
            Hs1[n][f] = fmaxf(h, 0.f);
        }
    }
    __syncthreads();
    {
        float acc[8] = {0, 0, 0, 0, 0, 0, 0, 0};
#pragma unroll 4
        for (int k = 0; k < 128; k += 4) {
            float4 w = *(const float4*)&oe_w1[f * 128 + k];
#pragma unroll
            for (int n = 0; n < 8; n++) {
                float4 x = *(const float4*)&Hs1[n][k];
                acc[n] += w.x * x.x + w.y * x.y + w.z * x.z + w.w * x.w;
            }
        }
        float b1 = oe_b1[f];
#pragma unroll
        for (int n = 0; n < 8; n++) {
            float o = fmaxf(acc[n] + b1, 0.f);
            Os[n][f] = o;
            g_obj[(base + n) * 128 + f] = o;
        }
    }
    __syncthreads();
    {
        float r[8] = {0, 0, 0, 0, 0, 0, 0, 0};
        float s[8] = {0, 0, 0, 0, 0, 0, 0, 0};
        const float* wrow = rp_w + f * 384;
#pragma unroll 4
        for (int k = 0; k < 128; k += 4) {
            float4 wr = *(const float4*)&wrow[128 + k];
            float4 ws = *(const float4*)&wrow[256 + k];
#pragma unroll
            for (int n = 0; n < 8; n++) {
                float4 o = *(const float4*)&Os[n][k];
                r[n] += wr.x * o.x + wr.y * o.y + wr.z * o.z + wr.w * o.w;
                s[n] += ws.x * o.x + ws.y * o.y + ws.z * o.z + ws.w * o.w;
            }
        }
        float bb = rp_b[f];
#pragma unroll
        for (int n = 0; n < 8; n++) {
            g_R[(base + n) * 128 + f] = r[n] + bb;
            g_S[(base + n) * 128 + f] = s[n];
        }
    }
}

// ---------------- fused rel encoder + edge-GEMM (fp16 m16n8k16) + edge-apply(step0) ----------------
// 4 bi / block, 512 threads, 16 warps, warp tile 32j x 64f.
// smem map (floats): Ebuf [0,32768) fp32 (phase-2, overlays Hs fp16 [0,17408))
//                    Wsm half @32768 (17408 halves = [32768,41472) floats; Ss fp32 overlays [32768,40960))
//                    Ps @41472 (2048), Us @43520 (512), Bss @44032 (128). total 44160 floats.
__global__ __launch_bounds__(512) void rel_fused_h(const float* __restrict__ rel_attrs,
                                                   const float* __restrict__ re_w0,
                                                   const float* __restrict__ re_b1,
                                                   const float* __restrict__ rp_lnw,
                                                   const float* __restrict__ rp_lnb) {
    extern __shared__ float dsm[];
    float* Ebuf = dsm;
    __half* Hs = (__half*)dsm;                 // 256 x 136 halves
    __half* Wsm = (__half*)(dsm + 32768);      // 128 x 136 halves
    float* Ss = dsm + 32768;                   // 8192 floats (phase 2)
    float* Ps = dsm + 41472;                   // 2048
    float* Us = dsm + 43520;                   // 512
    float* Bss = dsm + 44032;                  // 128
    uint32_t hs_base = (uint32_t)__cvta_generic_to_shared(Hs);
    uint32_t w_base = (uint32_t)__cvta_generic_to_shared(Wsm);

    int bi0 = blockIdx.x * 4;
    int tid = threadIdx.x;
    int b = bi0 >> 6;
    int lane = tid & 31, warp = tid >> 5;
    int jg = warp >> 1;   // 0..7: rows 32*jg..+31
    int ng = warp & 1;    // 0..1: cols 64*ng..+63

    Us[tid] = g_u[(bi0 + (tid >> 7)) * 128 + (tid & 127)];
    if (tid < 128) Bss[tid] = re_b1[tid];
    // load W1 (fp16) into Wsm, row stride 136 halves (272 B)
    {
        const uint4* src = (const uint4*)g_w1h;
#pragma unroll
        for (int i = 0; i < 4; i++) {
            int idx = i * 512 + tid;          // 2048 uint4 = 128 rows x 16
            int row = idx >> 4, part = idx & 15;
            *(uint4*)((char*)Wsm + row * 272 + part * 16) = src[idx];
        }
    }
    __syncthreads();

    // ---- build H[row][k] (fp16) ----
    {
        int bi_l = tid >> 7;
        int j = (tid >> 1) & 63;
        int kh = tid & 1;
        int row = bi_l * 64 + j;
        __half* hrow = Hs + row * 136 + kh * 64;
        float4 rv = *(const float4*)(rel_attrs + ((bi0 + bi_l) * 64 + j) * 4);
        const float* vt = g_vt + b * 8192 + j;
        const float* uu = Us + bi_l * 128;
#pragma unroll
        for (int kk = 0; kk < 64; kk += 8) {
            __half hv[8];
#pragma unroll
            for (int q = 0; q < 8; q++) {
                int k = kh * 64 + kk + q;
                const float* w = re_w0 + k * 20;
                float val = uu[k] + vt[k * 64] + rv.x * w[0] + rv.y * w[1] + rv.z * w[2] + rv.w * w[3];
                hv[q] = __float2half_rn(fmaxf(val, 0.f));
            }
            *(uint4*)(hrow + kk) = *(uint4*)hv;
        }
    }
    __syncthreads();

    // ldmatrix lane addressing (b16):
    // A tile (16m x 16k): lanes 0-7 rows m0.., k0; 8-15 rows m0+8.., k0; 16-23 m0.., k8; 24-31 m0+8.., k8
    int arow = (lane & 7) + ((lane >> 3) & 1) * 8;
    int akoff = (lane >> 4) * 8;
    uint32_t aA0 = hs_base + ((32 * jg + arow) * 136 + akoff) * 2;
    uint32_t aA1 = hs_base + ((32 * jg + 16 + arow) * 136 + akoff) * 2;
    // B tile (16f x 16k): lanes 0-7 f n0.., k0; 8-15 f n0.., k8; 16-23 f n0+8.., k0; 24-31 f n0+8.., k8
    int brow = ((lane >> 4) << 3) + (lane & 7);
    int bkoff = ((lane >> 3) & 1) * 8;
    uint32_t bA[4];
#pragma unroll
    for (int t = 0; t < 4; t++)
        bA[t] = w_base + ((64 * ng + 16 * t + brow) * 136 + bkoff) * 2;

    float d[2][8][4];

    // ================= GEMM1: rel = relu(b1 + H @ W1^T) =================
#pragma unroll
    for (int m = 0; m < 2; m++)
#pragma unroll
        for (int n = 0; n < 8; n++)
#pragma unroll
            for (int q = 0; q < 4; q++) d[m][n][q] = 0.f;
#pragma unroll
    for (int c = 0; c < 8; c++) {
        uint32_t ko = c * 32;   // 16 halves = 32 bytes per k-step
        uint32_t a[2][4];
        LDSM_X4(a[0], aA0 + ko);
        LDSM_X4(a[1], aA1 + ko);
#pragma unroll
        for (int t = 0; t < 4; t++) {
            uint32_t bb[4];
            LDSM_X4(bb, bA[t] + ko);
            MMA_F16(d[0][2 * t], a[0], bb[0], bb[1]);
            MMA_F16(d[1][2 * t], a[1], bb[0], bb[1]);
            MMA_F16(d[0][2 * t + 1], a[0], bb[2], bb[3]);
            MMA_F16(d[1][2 * t + 1], a[1], bb[2], bb[3]);
        }
    }
    __syncthreads();   // all Hs/Wsm reads of GEMM1 done

    // epilogue 1: bias + relu -> fp16 rel back into Hs; reload Wr into Wsm
#pragma unroll
    for (int m = 0; m < 2; m++) {
        int r0 = 32 * jg + 16 * m + (lane >> 2);
#pragma unroll
        for (int n = 0; n < 8; n++) {
            int f0 = 64 * ng + 8 * n + 2 * (lane & 3);
            float bb0 = Bss[f0], bb1 = Bss[f0 + 1];
            __half2 v01 = __floats2half2_rn(fmaxf(d[m][n][0] + bb0, 0.f),
                                            fmaxf(d[m][n][1] + bb1, 0.f));
            __half2 v23 = __floats2half2_rn(fmaxf(d[m][n][2] + bb0, 0.f),
                                            fmaxf(d[m][n][3] + bb1, 0.f));
            *(__half2*)(Hs + r0 * 136 + f0) = v01;
            *(__half2*)(Hs + (r0 + 8) * 136 + f0) = v23;
        }
    }
    {
        const uint4* src = (const uint4*)g_wrh;
#pragma unroll
        for (int i = 0; i < 4; i++) {
            int idx = i * 512 + tid;
            int row = idx >> 4, part = idx & 15;
            *(uint4*)((char*)Wsm + row * 272 + part * 16) = src[idx];
        }
    }
    __syncthreads();

    // ================= GEMM2: E = rel @ Wr^T =================
#pragma unroll
    for (int m = 0; m < 2; m++)
#pragma unroll
        for (int n = 0; n < 8; n++)
#pragma unroll
            for (int q = 0; q < 4; q++) d[m][n][q] = 0.f;
#pragma unroll
    for (int c = 0; c < 8; c++) {
        uint32_t ko = c * 32;
        uint32_t a[2][4];
        LDSM_X4(a[0], aA0 + ko);
        LDSM_X4(a[1], aA1 + ko);
#pragma unroll
        for (int t = 0; t < 4; t++) {
            uint32_t bb[4];
            LDSM_X4(bb, bA[t] + ko);
            MMA_F16(d[0][2 * t], a[0], bb[0], bb[1]);
            MMA_F16(d[1][2 * t], a[1], bb[0], bb[1]);
            MMA_F16(d[0][2 * t + 1], a[0], bb[2], bb[3]);
            MMA_F16(d[1][2 * t + 1], a[1], bb[2], bb[3]);
        }
    }
    __syncthreads();   // Hs/Wsm reads done; safe to overlay Ebuf / Ss

    // epilogue 2: E -> g_E and Ebuf[row][128]
    float* Ep = g_E + (long)bi0 * 8192;
#pragma unroll
    for (int m = 0; m < 2; m++) {
        int r0 = 32 * jg + 16 * m + (lane >> 2);
#pragma unroll
        for (int n = 0; n < 8; n++) {
            int f0 = 64 * ng + 8 * n + 2 * (lane & 3);
            float2 v01 = make_float2(d[m][n][0], d[m][n][1]);
            float2 v23 = make_float2(d[m][n][2], d[m][n][3]);
            *(float2*)&Ep[r0 * 128 + f0] = v01;
            *(float2*)&Ep[(r0 + 8) * 128 + f0] = v23;
            *(float2*)&Ebuf[r0 * 128 + f0] = v01;
            *(float2*)&Ebuf[(r0 + 8) * 128 + f0] = v23;
        }
    }
    // S (batch-shared) into Ss, R into Us
#pragma unroll
    for (int i = 0; i < 4; i++) {
        int idx4 = (i * 512 + tid) * 4;
        *(float4*)&Ss[idx4] = *(const float4*)&g_S[b * 8192 + idx4];
    }
    Us[tid] = g_R[bi0 * 128 + tid];
    __syncthreads();

    // ---- fused edge-apply step 0: Y = E + R_i + S_j, LN, relu, sum over j ----
    {
        int bi_l = warp >> 2;
        float4 rv = *(const float4*)&Us[bi_l * 128 + lane * 4];
        float4 lw = *(const float4*)&rp_lnw[lane * 4];
        float4 lb = *(const float4*)&rp_lnb[lane * 4];
        float ag0 = 0.f, ag1 = 0.f, ag2 = 0.f, ag3 = 0.f;
#pragma unroll 4
        for (int rr = 0; rr < 16; rr++) {
            int r = warp * 16 + rr;
            int j = r & 63;
            float4 e = *(const float4*)&Ebuf[r * 128 + lane * 4];
            float4 sv = *(const float4*)&Ss[j * 128 + lane * 4];
            float4 y = make_float4(e.x + rv.x + sv.x, e.y + rv.y + sv.y,
                                   e.z + rv.z + sv.z, e.w + rv.w + sv.w);
            float s = y.x + y.y + y.z + y.w;
            float ss = y.x * y.x + y.y * y.y + y.z * y.z + y.w * y.w;
#pragma unroll
            for (int off = 16; off; off >>= 1) {
                s += __shfl_xor_sync(0xffffffffu, s, off);
                ss += __shfl_xor_sync(0xffffffffu, ss, off);
            }
            float mu = s * 0.0078125f;
            float var = ss * 0.0078125f - mu * mu;
            float rstd = rsqrtf(var + 1e-5f);
            ag0 += fmaxf((y.x - mu) * rstd * lw.x + lb.x, 0.f);
            ag1 += fmaxf((y.y - mu) * rstd * lw.y + lb.y, 0.f);
            ag2 += fmaxf((y.z - mu) * rstd * lw.z + lb.z, 0.f);
            ag3 += fmaxf((y.w - mu) * rstd * lw.w + lb.w, 0.f);
        }
        *(float4*)&Ps[warp * 128 + lane * 4] = make_float4(ag0, ag1, ag2, ag3);
    }
    __syncthreads();
    {
        int bi_l = tid >> 7, f = tid & 127;
        g_agg[(bi0 + bi_l) * 128 + f] =
            Ps[(4 * bi_l) * 128 + f] + Ps[(4 * bi_l + 1) * 128 + f] +
            Ps[(4 * bi_l + 2) * 128 + f] + Ps[(4 * bi_l + 3) * 128 + f];
    }
}

// ---------------- edge apply (step 1) ----------------
__global__ __launch_bounds__(128) void edge_apply_kernel(const float* __restrict__ rp_lnw,
                                                         const float* __restrict__ rp_lnb) {
    __shared__ float Rs[128];
    __shared__ float Ps[512];
    int bi = blockIdx.x;
    int tid = threadIdx.x;
    int b = bi >> 6;
    int warp = tid >> 5, lane = tid & 31;
    Rs[tid] = g_R[bi * 128 + tid];
    __syncthreads();
    float4 rv = *(const float4*)&Rs[lane * 4];
    float4 lw = *(const float4*)&rp_lnw[lane * 4];
    float4 lb = *(const float4*)&rp_lnb[lane * 4];
    const float* Ep = g_E + (long)bi * 8192;
    float ag0 = 0.f, ag1 = 0.f, ag2 = 0.f, ag3 = 0.f;
#pragma unroll 4
    for (int r = 0; r < 16; r++) {
        int j = warp * 16 + r;
        float4 e = *(const float4*)&Ep[j * 128 + lane * 4];
        float4 sv = *(const float4*)&g_S[(b * 64 + j) * 128 + lane * 4];
        float4 y = make_float4(e.x + rv.x + sv.x, e.y + rv.y + sv.y,
                               e.z + rv.z + sv.z, e.w + rv.w + sv.w);
        float s = y.x + y.y + y.z + y.w;
        float ss = y.x * y.x + y.y * y.y + y.z * y.z + y.w * y.w;
#pragma unroll
        for (int off = 16; off; off >>= 1) {
            s += __shfl_xor_sync(0xffffffffu, s, off);
            ss += __shfl_xor_sync(0xffffffffu, ss, off);
        }
        float mu = s * 0.0078125f;
        float var = ss * 0.0078125f - mu * mu;
        float rstd = rsqrtf(var + 1e-5f);
        ag0 += fmaxf((y.x - mu) * rstd * lw.x + lb.x, 0.f);
        ag1 += fmaxf((y.y - mu) * rstd * lw.y + lb.y, 0.f);
        ag2 += fmaxf((y.z - mu) * rstd * lw.z + lb.z, 0.f);
        ag3 += fmaxf((y.w - mu) * rstd * lw.w + lb.w, 0.f);
    }
    *(float4*)&Ps[warp * 128 + lane * 4] = make_float4(ag0, ag1, ag2, ag3);
    __syncthreads();
    g_agg[bi * 128 + tid] = Ps[tid] + Ps[128 + tid] + Ps[256 + tid] + Ps[384 + tid];
}

// ---------------- fused object update (+rs or +predict): 16 nodes/block, 512 thr, k-split ----------------
__global__ __launch_bounds__(512) void obj_update_f(const float* __restrict__ pp_w,
                                                    const float* __restrict__ pp_b,
                                                    const float* __restrict__ pp_lnw,
                                                    const float* __restrict__ pp_lnb,
                                                    const float* __restrict__ rp_w,
                                                    const float* __restrict__ rp_b,
                                                    const float* __restrict__ pr_w0,
                                                    const float* __restrict__ pr_b0,
                                                    const float* __restrict__ pr_w1,
                                                    const float* __restrict__ pr_b1,
                                                    float* __restrict__ out,
                                                    int mode) {  // 0: +rs, 1: +predict
    extern __shared__ float sm[];
    float* Xs   = sm;            // [16][256]
    float* part = sm + 4096;     // 8192
    float* Cs   = sm + 12288;    // [16][128]
    float* Os2  = sm + 14336;    // [16][128]
    float* Hs2  = sm + 16384;    // [16][128]
    int base = blockIdx.x * 16;
    int tid = threadIdx.x;
    int warp = tid >> 5, lane = tid & 31;

#pragma unroll
    for (int i = 0; i < 8; i++) {
        int idx = i * 512 + tid;
        int n = idx >> 8, c = idx & 255;
        Xs[idx] = (c < 128) ? g_obj[(base + n) * 128 + c]
                            : g_agg[(base + n) * 128 + (c - 128)];
    }
    __syncthreads();

    {
        int f = tid & 127, q = tid >> 7;
        float acc[16];
#pragma unroll
        for (int n = 0; n < 16; n++) acc[n] = 0.f;
        const float* wrow = pp_w + f * 256 + q * 64;
        const float* xb = Xs + q * 64;
#pragma unroll 4
        for (int k = 0; k < 64; k += 4) {
            float4 w = *(const float4*)&wrow[k];
#pragma unroll
            for (int n = 0; n < 16; n++) {
                float4 x = *(const float4*)&xb[n * 256 + k];
                acc[n] += w.x * x.x + w.y * x.y + w.z * x.z + w.w * x.w;
            }
        }
#pragma unroll
        for (int n = 0; n < 16; n++) part[q * 2048 + n * 128 + f] = acc[n];
    }
    __syncthreads();
#pragma unroll
    for (int i = 0; i < 4; i++) {
        int idx = i * 512 + tid;
        float v = part[idx] + part[2048 + idx] + part[4096 + idx] + part[6144 + idx];
        Cs[idx] = v + pp_b[idx & 127];
    }
    __syncthreads();

    {
        float4 lw = *(const float4*)&pp_lnw[lane * 4];
        float4 lb = *(const float4*)&pp_lnb[lane * 4];
        int n = warp;
        float4 y = *(const float4*)&Cs[n * 128 + lane * 4];
        float s = y.x + y.y + y.z + y.w;
        float ss = y.x * y.x + y.y * y.y + y.z * y.z + y.w * y.w;
#pragma unroll
        for (int off = 16; off; off >>= 1) {
            s += __shfl_xor_sync(0xffffffffu, s, off);
            ss += __shfl_xor_sync(0xffffffffu, ss, off);
        }
        float mu = s * 0.0078125f;
        float var = ss * 0.0078125f - mu * mu;
        float rstd = rsqrtf(var + 1e-5f);
        float4 o = make_float4(fmaxf((y.x - mu) * rstd * lw.x + lb.x, 0.f),
                               fmaxf((y.y - mu) * rstd * lw.y + lb.y, 0.f),
                               fmaxf((y.z - mu) * rstd * lw.z + lb.z, 0.f),
                               fmaxf((y.w - mu) * rstd * lw.w + lb.w, 0.f));
        *(float4*)&Os2[n * 128 + lane * 4] = o;
        if (mode == 0) *(float4*)&g_obj[(base + n) * 128 + lane * 4] = o;
    }
    __syncthreads();

    if (mode == 0) {
        int fo = tid & 255, q = tid >> 8;
        float acc[16];
#pragma unroll
        for (int n = 0; n < 16; n++) acc[n] = 0.f;
        const float* wrow = (fo < 128) ? (rp_w + fo * 384 + 128 + q * 64)
                                       : (rp_w + (fo - 128) * 384 + 256 + q * 64);
        const float* ob = Os2 + q * 64;
#pragma unroll 4
        for (int k = 0; k < 64; k += 4) {
            float4 w = *(const float4*)&wrow[k];
#pragma unroll
            for (int n = 0; n < 16; n++) {
                float4 x = *(const float4*)&ob[n * 128 + k];
                acc[n] += w.x * x.x + w.y * x.y + w.z * x.z + w.w * x.w;
            }
        }
#pragma unroll
        for (int n = 0; n < 16; n++) part[q * 4096 + n * 256 + fo] = acc[n];
        __syncthreads();
#pragma unroll
        for (int i = 0; i < 8; i++) {
            int idx = i * 512 + tid;
            float v = part[idx] + part[4096 + idx];
            int n = idx >> 8, fo2 = idx & 255;
            if (fo2 < 128) g_R[(base + n) * 128 + fo2] = v + rp_b[fo2];
            else g_S[(base + n) * 128 + fo2 - 128] = v;
        }
    } else {
        {
            int f = tid & 127, q = tid >> 7;
            float acc[16];
#pragma unroll
            for (int n = 0; n < 16; n++) acc[n] = 0.f;
            const float* wrow = pr_w0 + f * 128 + q * 32;
            const float* ob = Os2 + q * 32;
#pragma unroll 4
            for (int k = 0; k < 32; k += 4) {
                float4 w = *(const float4*)&wrow[k];
#pragma unroll
                for (int n = 0; n < 16; n++) {
                    float4 x = *(const float4*)&ob[n * 128 + k];
                    acc[n] += w.x * x.x + w.y * x.y + w.z * x.z + w.w * x.w;
                }
            }
#pragma unroll
            for (int n = 0; n < 16; n++) part[q * 2048 + n * 128 + f] = acc[n];
        }
        __syncthreads();
#pragma unroll
        for (int i = 0; i < 4; i++) {
            int idx = i * 512 + tid;
            float v = part[idx] + part[2048 + idx] + part[4096 + idx] + part[6144 + idx];
            Hs2[idx] = fmaxf(v + pr_b0[idx & 127], 0.f);
        }
        __syncthreads();
        {
            int n = tid >> 5, op = tid & 31;
            float a0 = 0.f;
            const float* wp = pr_w1 + op * 128;
#pragma unroll 4
            for (int k = 0; k < 128; k += 4) {
                float4 x = *(const float4*)&Hs2[n * 128 + k];
                float4 w = *(const float4*)&wp[k];
                a0 += w.x * x.x + w.y * x.y + w.z * x.z + w.w * x.w;
            }
            out[(base + n) * 32 + op] = tanhf(a0 + pr_b1[op]);
        }
    }
}

// ---------------- launch ----------------
extern "C" void kernel_launch(void* const* d_in, const int* in_sizes, int n_in,
                              void* d_out, int out_size) {
    const float* attrs     = (const float*)d_in[0];
    const float* states    = (const float*)d_in[1];
    const float* rel_attrs = (const float*)d_in[3];
    const float* oe_w0 = (const float*)d_in[4];
    const float* oe_b0 = (const float*)d_in[5];
    const float* oe_w1 = (const float*)d_in[6];
    const float* oe_b1 = (const float*)d_in[7];
    const float* re_w0 = (const float*)d_in[8];
    const float* re_b0 = (const float*)d_in[9];
    const float* re_w1 = (const float*)d_in[10];
    const float* re_b1 = (const float*)d_in[11];
    const float* rp_w  = (const float*)d_in[12];
    const float* rp_b  = (const float*)d_in[13];
    const float* rp_lnw = (const float*)d_in[14];
    const float* rp_lnb = (const float*)d_in[15];
    const float* pp_w  = (const float*)d_in[16];
    const float* pp_b  = (const float*)d_in[17];
    const float* pp_lnw = (const float*)d_in[18];
    const float* pp_lnb = (const float*)d_in[19];
    const float* pr_w0 = (const float*)d_in[20];
    const float* pr_b0 = (const float*)d_in[21];
    const float* pr_w1 = (const float*)d_in[22];
    const float* pr_b1 = (const float*)d_in[23];
    float* out = (float*)d_out;

    const int dsm_bytes = 44160 * 4;   // ~172.5 KB
    const int ou_bytes  = 18432 * 4;   // 72 KB
    cudaFuncSetAttribute(rel_fused_h, cudaFuncAttributeMaxDynamicSharedMemorySize, dsm_bytes);
    cudaFuncSetAttribute(obj_update_f, cudaFuncAttributeMaxDynamicSharedMemorySize, ou_bytes);

    prep_kernel<<<2, 256>>>(re_w1, rp_w);
    encode_all<<<256, 128>>>(attrs, states, re_w0, re_b0, oe_w0, oe_b0, oe_w1, oe_b1, rp_w, rp_b);
    rel_fused_h<<<512, 512, dsm_bytes>>>(rel_attrs, re_w0, re_b1, rp_lnw, rp_lnb);
    obj_update_f<<<128, 512, ou_bytes>>>(pp_w, pp_b, pp_lnw, pp_lnb, rp_w, rp_b,
                                         pr_w0, pr_b0, pr_w1, pr_b1, out, 0);
    edge_apply_kernel<<<NNODES, 128>>>(rp_lnw, rp_lnb);
    obj_update_f<<<128, 512, ou_bytes>>>(pp_w, pp_b, pp_lnw, pp_lnb, rp_w, rp_b,
                                         pr_w0, pr_b0, pr_w1, pr_b1, out, 1);
}